// round 8
// baseline (speedup 1.0000x reference)
#include <cuda_runtime.h>
#include <math.h>
#include <stdint.h>

// Problem constants
#define U      128
#define NC     10
#define NF     3
#define TT     1000
#define BB     256
#define CSZ    4              // CTAs per cluster
#define GC     8              // batch elements per cluster
#define OWN    32             // units owned per CTA
#define NTHR   512
#define NCTA   128            // (BB/GC)*CSZ

#define R_ON_   0.05f
#define ALPHA_  0.001f
#define LN_EPS_ 1e-3f

// ---- packed f32x2 helpers (FFMA2: 2x fp32 MAC throughput) ----
__device__ __forceinline__ unsigned long long pack2(float a, float b) {
    unsigned long long r;
    asm("mov.b64 %0, {%1, %2};" : "=l"(r) : "f"(a), "f"(b));
    return r;
}
__device__ __forceinline__ float2 unpack2(unsigned long long v) {
    float2 r;
    asm("mov.b64 {%0, %1}, %2;" : "=f"(r.x), "=f"(r.y) : "l"(v));
    return r;
}
__device__ __forceinline__ void fma2p(unsigned long long& acc,
                                      unsigned long long a,
                                      unsigned long long b) {
    asm("fma.rn.f32x2 %0, %1, %2, %0;" : "+l"(acc) : "l"(a), "l"(b));
}

__device__ __forceinline__ float sigmoidf_(float x) { return 1.0f / (1.0f + expf(-x)); }

#define CLUSTER_SYNC() do { \
    asm volatile("barrier.cluster.arrive.aligned;" ::: "memory"); \
    asm volatile("barrier.cluster.wait.aligned;"   ::: "memory"); } while (0)

__device__ __forceinline__ void st_cluster_f32(uint32_t laddr, uint32_t r, float v) {
    uint32_t ra;
    asm volatile("mapa.shared::cluster.u32 %0, %1, %2;" : "=r"(ra) : "r"(laddr), "r"(r));
    asm volatile("st.shared::cluster.f32 [%0], %1;" :: "r"(ra), "f"(v) : "memory");
}
// store v to the same SMEM slot in all 4 cluster CTAs (incl. self)
__device__ __forceinline__ void bcast4_f32(void* p, float v) {
    uint32_t a = (uint32_t)__cvta_generic_to_shared(p);
    #pragma unroll
    for (uint32_t r = 0; r < CSZ; ++r) st_cluster_f32(a, r, v);
}

// Dynamic SMEM layout: 57952 floats = 231808 B  (<= 232448 B limit, 1 CTA/SM)
struct __align__(16) SM {
    float Wh0s[128 * 128];      // own 128 cols (gate-interleaved) of Wh0, [k][lc]
    float Wx1s[128 * 128];
    float Wh1s[128 * 128];
    float z[2 * 8 * 128];       // [ks][b][lc] gate pre-activation partials
    float h0f[2][128 * 8];      // full h0, [unit][b], double-buffered by t-parity
    float h1f[2][128 * 8];
    float h0l[GC * OWN], h1l[GC * OWN];  // own-unit state [b][j]
    float c0l[GC * OWN], c1l[GC * OWN];
    float Wx0s[NF * 128];       // own cols of Wx0 [f][lc]
    float b0s[128], b1s[128];   // own cols of biases
    float tau0s[OWN], s0s[OWN], tau1s[OWN], s1s[OWN];
    float gmf[128], btf[128];   // full gamma/beta
    float Wfcs[OWN * NC];       // own rows of Wfc
    float bfcs[16];
    float red_s[CSZ * GC], red_q[CSZ * GC];   // LN partials [srcRank][b]
    float lrecv[CSZ * 2 * 16];  // logit partials [srcRank][localBatch][c pad16]
    float xb[2][GC][4];         // double-buffered inputs (f padded to 4)
    float tmb[2][GC];           // double-buffered times
};

// One 64-row K-slab of  hf[128 units][8 b]  @  Ws[128][128 own cols],
// 1 col x 4 batches per thread. acc[p] = f32x2 over batches (hb+2p, hb+2p+1).
// hf must be pre-offset by the batch half (0 or 4).
__device__ __forceinline__ void mv_pass4(const float* __restrict__ Ws,
                                         const float* __restrict__ hf,
                                         int kbase, int lc,
                                         unsigned long long acc[2]) {
    const float* w = Ws + kbase * 128 + lc;
    const float* h = hf + kbase * 8;
    #pragma unroll 8
    for (int k = 0; k < 64; ++k) {
        float wv = w[k * 128];
        unsigned long long wd = pack2(wv, wv);
        ulonglong2 hp = *reinterpret_cast<const ulonglong2*>(h + k * 8); // 4 batches
        fma2p(acc[0], wd, hp.x);
        fma2p(acc[1], wd, hp.y);
    }
}

__device__ __forceinline__ void plstm_gate2(float zi, float zf, float zg, float zo,
                                            float tcur, float tau, float s,
                                            float& h, float& c) {
    float ch = sigmoidf_(zf) * c + sigmoidf_(zi) * tanhf(zg);
    float hh = sigmoidf_(zo) * tanhf(ch);
    float d = tcur - s;
    float m = fmodf(d, tau);
    if (m < 0.0f) m += tau;           // python-style mod (divisor > 0)
    float phi = m / tau;
    float kg;
    if (phi < 0.5f * R_ON_)      kg = 2.0f * phi / R_ON_;
    else if (phi < R_ON_)        kg = 2.0f - 2.0f * phi / R_ON_;
    else                         kg = ALPHA_ * phi;
    h = kg * hh + (1.0f - kg) * h;
    c = kg * ch + (1.0f - kg) * c;
}

__global__ void __launch_bounds__(NTHR, 1) __cluster_dims__(CSZ, 1, 1)
plstm_cluster_kernel(const float* __restrict__ inputs, const float* __restrict__ times,
                     const float* __restrict__ gWx0, const float* __restrict__ gWh0,
                     const float* __restrict__ gb0,  const float* __restrict__ gtau0,
                     const float* __restrict__ gs0,  const float* __restrict__ gWx1,
                     const float* __restrict__ gWh1, const float* __restrict__ gb1,
                     const float* __restrict__ gtau1,const float* __restrict__ gs1,
                     const float* __restrict__ ggamma,const float* __restrict__ gbeta,
                     const float* __restrict__ gWfc, const float* __restrict__ gbfc,
                     float* __restrict__ out) {
    extern __shared__ float smraw[];
    SM& sm = *reinterpret_cast<SM*>(smraw);
    const int tid = threadIdx.x;
    uint32_t rank;
    asm("mov.u32 %0, %%cluster_ctarank;" : "=r"(rank));
    const int bstart = (blockIdx.x >> 2) * GC;

    // ---- one-time SMEM setup: this CTA's column slabs (gate-interleaved) ----
    for (int i = tid; i < 128 * 128; i += NTHR) {
        int k = i >> 7, lc = i & 127;
        int gcol = ((lc >> 5) << 7) + ((int)rank << 5) + (lc & 31);
        sm.Wh0s[i] = gWh0[k * 512 + gcol];
        sm.Wx1s[i] = gWx1[k * 512 + gcol];
        sm.Wh1s[i] = gWh1[k * 512 + gcol];
    }
    for (int i = tid; i < NF * 128; i += NTHR) {
        int f = i >> 7, lc = i & 127;
        int gcol = ((lc >> 5) << 7) + ((int)rank << 5) + (lc & 31);
        sm.Wx0s[i] = gWx0[f * 512 + gcol];
    }
    for (int lc = tid; lc < 128; lc += NTHR) {
        int gcol = ((lc >> 5) << 7) + ((int)rank << 5) + (lc & 31);
        sm.b0s[lc] = gb0[gcol];
        sm.b1s[lc] = gb1[gcol];
        sm.gmf[lc] = ggamma[lc];
        sm.btf[lc] = gbeta[lc];
    }
    if (tid < OWN) {
        int u = (int)rank * OWN + tid;
        sm.tau0s[tid] = gtau0[u]; sm.s0s[tid] = gs0[u];
        sm.tau1s[tid] = gtau1[u]; sm.s1s[tid] = gs1[u];
    }
    for (int i = tid; i < OWN * NC; i += NTHR) {
        int j = i / NC, c2 = i - j * NC;
        sm.Wfcs[i] = gWfc[((int)rank * OWN + j) * NC + c2];
    }
    if (tid < NC) sm.bfcs[tid] = gbfc[tid];
    for (int i = tid; i < 128 * 8; i += NTHR) {
        sm.h0f[0][i] = 0.0f; sm.h0f[1][i] = 0.0f;
        sm.h1f[0][i] = 0.0f; sm.h1f[1][i] = 0.0f;
    }
    if (tid < GC * OWN) {
        sm.h0l[tid] = 0.0f; sm.h1l[tid] = 0.0f;
        sm.c0l[tid] = 0.0f; sm.c1l[tid] = 0.0f;
    }
    if (tid < GC) sm.tmb[0][tid] = times[(size_t)(bstart + tid) * TT];
    if (tid < GC * NF) {
        int g = tid / NF, f = tid - g * NF;
        sm.xb[0][g][f] = inputs[((size_t)(bstart + g) * TT) * NF + f];
    }
    __syncthreads();
    CLUSTER_SYNC();   // all CTAs' zero-init done before any remote writes land

    // matvec mapping: 512 threads = (batch half) x (k slab) x (128 cols)
    const int half  = tid >> 8;            // batch quad: 0 -> b0..3, 1 -> b4..7
    const int ks    = (tid >> 7) & 1;      // K slab (64 rows)
    const int lc    = tid & 127;           // own column
    const int kbase = ks << 6;
    const int hoff  = half << 2;           // batch offset into 8-wide rows
    // gate mapping (first 8 warps): warp gb = batch, lane gj = own unit
    const int gb = tid >> 5, gj = tid & 31;
    // LN/hn mapping: 2 values per thread
    const int hk = tid >> 2, hb2 = (tid & 3) << 1;

    for (int t = 0; t < TT; ++t) {
        const int par = t & 1, parn = par ^ 1;

        // ============ layer 0 matvec: z0 = x@Wx0 + h0@Wh0 + b0 (own cols) ============
        unsigned long long acc[2];
        if (ks == 0) {
            float w0 = sm.Wx0s[lc], w1 = sm.Wx0s[128 + lc], w2 = sm.Wx0s[256 + lc];
            float bz = sm.b0s[lc];
            float a[4];
            #pragma unroll
            for (int q = 0; q < 4; ++q) {
                const float* xq = sm.xb[par][hoff + q];
                a[q] = bz + xq[0] * w0 + xq[1] * w1 + xq[2] * w2;
            }
            acc[0] = pack2(a[0], a[1]);
            acc[1] = pack2(a[2], a[3]);
        } else {
            acc[0] = 0ull; acc[1] = 0ull;
        }
        mv_pass4(sm.Wh0s, sm.h0f[par] + hoff, kbase, lc, acc);
        {
            float2 v0 = unpack2(acc[0]), v1 = unpack2(acc[1]);
            float* zp = sm.z + (ks * 8 + hoff) * 128 + lc;
            zp[0]   = v0.x; zp[128] = v0.y;
            zp[256] = v1.x; zp[384] = v1.y;
        }
        // prefetch next step's x/t
        if (t + 1 < TT) {
            if (tid < GC) sm.tmb[parn][tid] = times[(size_t)(bstart + tid) * TT + t + 1];
            if (tid < GC * NF) {
                int g = tid / NF, f = tid - g * NF;
                sm.xb[parn][g][f] = inputs[((size_t)(bstart + g) * TT + t + 1) * NF + f];
            }
        }
        __syncthreads();                           // B1: z0 ready

        // ============ layer 0 gates (own units) + h0 exchange + LN partials ============
        if (tid < 256) {
            const float* zb = sm.z + gb * 128;
            float zi = zb[gj]      + zb[1024 + gj];
            float zf = zb[32 + gj] + zb[1024 + 32 + gj];
            float zg = zb[64 + gj] + zb[1024 + 64 + gj];
            float zo = zb[96 + gj] + zb[1024 + 96 + gj];
            float h = sm.h0l[gb * OWN + gj], c = sm.c0l[gb * OWN + gj];
            plstm_gate2(zi, zf, zg, zo, sm.tmb[par][gb], sm.tau0s[gj], sm.s0s[gj], h, c);
            sm.h0l[gb * OWN + gj] = h; sm.c0l[gb * OWN + gj] = c;
            int u = (int)rank * OWN + gj;
            bcast4_f32(&sm.h0f[parn][u * 8 + gb], h);
            float s = h, q = h * h;
            #pragma unroll
            for (int o = 16; o; o >>= 1) {
                s += __shfl_xor_sync(0xffffffffu, s, o);
                q += __shfl_xor_sync(0xffffffffu, q, o);
            }
            if (gj == 0) {
                bcast4_f32(&sm.red_s[rank * GC + gb], s);
                bcast4_f32(&sm.red_q[rank * GC + gb], q);
            }
        }
        CLUSTER_SYNC();                            // S1: h0f[parn] + LN partials visible

        // ============ LayerNorm -> hn (redundant per CTA; hn aliases h0f[par]) ============
        {
            float mu[2], rs[2];
            #pragma unroll
            for (int q = 0; q < 2; ++q) {
                int b = hb2 + q;
                float s  = sm.red_s[b] + sm.red_s[8 + b] + sm.red_s[16 + b] + sm.red_s[24 + b];
                float sq = sm.red_q[b] + sm.red_q[8 + b] + sm.red_q[16 + b] + sm.red_q[24 + b];
                float m = s * (1.0f / 128.0f);
                float v = fmaxf(sq * (1.0f / 128.0f) - m * m, 0.0f);
                mu[q] = m; rs[q] = rsqrtf(v + LN_EPS_);
            }
            float2 hv = *reinterpret_cast<const float2*>(&sm.h0f[parn][hk * 8 + hb2]);
            float gm = sm.gmf[hk], bt = sm.btf[hk];
            float2 hn;
            hn.x = gm * (hv.x - mu[0]) * rs[0] + bt;
            hn.y = gm * (hv.y - mu[1]) * rs[1] + bt;
            *reinterpret_cast<float2*>(&sm.h0f[par][hk * 8 + hb2]) = hn;
        }
        __syncthreads();                           // B2: hn ready

        // ============ layer 1 matvec: z1 = hn@Wx1 + h1@Wh1 + b1 (own cols) ============
        if (ks == 0) {
            float bz = sm.b1s[lc];
            acc[0] = pack2(bz, bz);
            acc[1] = acc[0];
        } else {
            acc[0] = 0ull; acc[1] = 0ull;
        }
        mv_pass4(sm.Wx1s, sm.h0f[par] + hoff, kbase, lc, acc);   // hn lives in h0f[par]
        mv_pass4(sm.Wh1s, sm.h1f[par] + hoff, kbase, lc, acc);
        {
            float2 v0 = unpack2(acc[0]), v1 = unpack2(acc[1]);
            float* zp = sm.z + (ks * 8 + hoff) * 128 + lc;
            zp[0]   = v0.x; zp[128] = v0.y;
            zp[256] = v1.x; zp[384] = v1.y;
        }
        __syncthreads();                           // B3: z1 ready

        // ============ layer 1 gates (own units) + h1 exchange ============
        if (tid < 256) {
            const float* zb = sm.z + gb * 128;
            float zi = zb[gj]      + zb[1024 + gj];
            float zf = zb[32 + gj] + zb[1024 + 32 + gj];
            float zg = zb[64 + gj] + zb[1024 + 64 + gj];
            float zo = zb[96 + gj] + zb[1024 + 96 + gj];
            float h = sm.h1l[gb * OWN + gj], c = sm.c1l[gb * OWN + gj];
            plstm_gate2(zi, zf, zg, zo, sm.tmb[par][gb], sm.tau1s[gj], sm.s1s[gj], h, c);
            sm.h1l[gb * OWN + gj] = h; sm.c1l[gb * OWN + gj] = c;
            int u = (int)rank * OWN + gj;
            bcast4_f32(&sm.h1f[parn][u * 8 + gb], h);
        }
        __syncthreads();                           // B4: h1l ready for FC

        // ============ FC partials over own 32 units -> owner rank ============
        if (tid < 80) {
            int fb = tid / 10, fc = tid - fb * 10;
            float a = 0.0f;
            #pragma unroll
            for (int jj = 0; jj < OWN; ++jj)
                a += sm.h1l[fb * OWN + jj] * sm.Wfcs[jj * NC + fc];
            int owner = fb >> 1, bL = fb & 1;
            uint32_t ad = (uint32_t)__cvta_generic_to_shared(
                &sm.lrecv[((int)rank * 2 + bL) * 16 + fc]);
            st_cluster_f32(ad, (uint32_t)owner, a);
        }
        CLUSTER_SYNC();                            // S2: h1f[parn] + logit partials visible

        // ============ softmax + output for this CTA's 2 batches ============
        if (tid < 2) {
            float lg[NC], mx = -1e30f;
            #pragma unroll
            for (int c2 = 0; c2 < NC; ++c2) {
                float v = sm.bfcs[c2]
                        + sm.lrecv[(0 + tid) * 16 + c2] + sm.lrecv[(2 + tid) * 16 + c2]
                        + sm.lrecv[(4 + tid) * 16 + c2] + sm.lrecv[(6 + tid) * 16 + c2];
                lg[c2] = v; mx = fmaxf(mx, v);
            }
            float e[NC], ssum = 0.0f;
            #pragma unroll
            for (int c2 = 0; c2 < NC; ++c2) { e[c2] = expf(lg[c2] - mx); ssum += e[c2]; }
            float inv = 1.0f / ssum;
            float* op = out + ((size_t)(bstart + (int)rank * 2 + tid) * TT + t) * NC;
            #pragma unroll
            for (int c2 = 0; c2 < NC; ++c2) op[c2] = e[c2] * inv;
        }
        // next iteration's first SMEM writes (z) happen only after all threads passed S2
    }
}

extern "C" void kernel_launch(void* const* d_in, const int* in_sizes, int n_in,
                              void* d_out, int out_size) {
    const float* inputs = (const float*)d_in[0];
    const float* times  = (const float*)d_in[1];
    const float* Wx0    = (const float*)d_in[2];
    const float* Wh0    = (const float*)d_in[3];
    const float* b0     = (const float*)d_in[4];
    const float* tau0   = (const float*)d_in[5];
    const float* s0     = (const float*)d_in[6];
    const float* Wx1    = (const float*)d_in[7];
    const float* Wh1    = (const float*)d_in[8];
    const float* b1     = (const float*)d_in[9];
    const float* tau1   = (const float*)d_in[10];
    const float* s1     = (const float*)d_in[11];
    const float* gamma  = (const float*)d_in[12];
    const float* beta   = (const float*)d_in[13];
    const float* Wfc    = (const float*)d_in[14];
    const float* bfc    = (const float*)d_in[15];

    cudaFuncSetAttribute(plstm_cluster_kernel,
                         cudaFuncAttributeMaxDynamicSharedMemorySize,
                         (int)sizeof(SM));
    plstm_cluster_kernel<<<NCTA, NTHR, sizeof(SM)>>>(
        inputs, times, Wx0, Wh0, b0, tau0, s0,
        Wx1, Wh1, b1, tau1, s1, gamma, beta, Wfc, bfc, (float*)d_out);
}

// round 9
// speedup vs baseline: 1.1774x; 1.1774x over previous
#include <cuda_runtime.h>
#include <math.h>
#include <stdint.h>

// Problem constants
#define U      128
#define NC     10
#define NF     3
#define TT     1000
#define BB     256
#define CSZ    4              // CTAs per cluster
#define GC     8              // batch elements per cluster
#define OWN    32             // units owned per CTA
#define NTHR   256
#define NCTA   128            // (BB/GC)*CSZ

#define R_ON_   0.05f
#define ALPHA_  0.001f
#define LN_EPS_ 1e-3f

// ---- packed f32x2 helpers (FFMA2: 2x fp32 MAC throughput) ----
__device__ __forceinline__ unsigned long long pack2(float a, float b) {
    unsigned long long r;
    asm("mov.b64 %0, {%1, %2};" : "=l"(r) : "f"(a), "f"(b));
    return r;
}
__device__ __forceinline__ float2 unpack2(unsigned long long v) {
    float2 r;
    asm("mov.b64 {%0, %1}, %2;" : "=f"(r.x), "=f"(r.y) : "l"(v));
    return r;
}
__device__ __forceinline__ void fma2p(unsigned long long& acc,
                                      unsigned long long a,
                                      unsigned long long b) {
    asm("fma.rn.f32x2 %0, %1, %2, %0;" : "+l"(acc) : "l"(a), "l"(b));
}

__device__ __forceinline__ float sigmoidf_(float x) { return 1.0f / (1.0f + expf(-x)); }

#define CLUSTER_ARRIVE() asm volatile("barrier.cluster.arrive.aligned;" ::: "memory")
#define CLUSTER_WAIT()   asm volatile("barrier.cluster.wait.aligned;"   ::: "memory")
#define CLUSTER_SYNC()   do { CLUSTER_ARRIVE(); CLUSTER_WAIT(); } while (0)

__device__ __forceinline__ void st_cluster_f32(uint32_t laddr, uint32_t r, float v) {
    uint32_t ra;
    asm volatile("mapa.shared::cluster.u32 %0, %1, %2;" : "=r"(ra) : "r"(laddr), "r"(r));
    asm volatile("st.shared::cluster.f32 [%0], %1;" :: "r"(ra), "f"(v) : "memory");
}
// store v to the same SMEM slot in all 4 cluster CTAs (incl. self)
__device__ __forceinline__ void bcast4_f32(void* p, float v) {
    uint32_t a = (uint32_t)__cvta_generic_to_shared(p);
    #pragma unroll
    for (uint32_t r = 0; r < CSZ; ++r) st_cluster_f32(a, r, v);
}

// Dynamic SMEM: 57984 floats = 231936 B  (<= 232448 B limit, 1 CTA/SM)
struct __align__(16) SM {
    float Wh0s[128 * 128];      // own 128 cols (gate-interleaved) of Wh0, [k][lc]
    float Wx1g[128 * 128];      // own cols of Wx1 * gamma[k]
    float Wh1s[128 * 128];
    float z[2 * 8 * 128];       // [ks][b][lc] gate pre-activation partials
    float h0f[2][128 * 8];      // full h0, [unit][b], double-buffered by t-parity
    float h1f[2][128 * 8];
    float c0l[GC * OWN], c1l[GC * OWN];  // own-unit cell state [b][j]
    float Wx0s[NF * 128];       // own cols of Wx0 [f][lc]
    float b0s[128], b1s[128];   // own cols of biases
    float S1cs[2][128];         // per-slab col sums of Wx1g
    float S2cs[2][128];         // per-slab col sums of Wx1*beta
    float tau0s[OWN], s0s[OWN], tau1s[OWN], s1s[OWN];
    float gmf[128], btf[128];   // full gamma/beta (precompute only)
    float Wfcs[OWN * NC + 32];  // own rows of Wfc (padded for OOB-safe reads)
    float bfcs[16];
    float red_s[CSZ * GC], red_q[CSZ * GC];   // LN partials [srcRank][b]
    float lrecv[CSZ * 2 * 16];  // logit partials [srcRank][localBatch][c pad16]
    float xb[2][GC][4];         // double-buffered inputs (f padded to 4)
    float tmb[2][GC];           // double-buffered times
};

// One 64-row K-slab of  hf[128 units][8 b]  @  Ws[128][128 own cols], 1 col/thread.
// acc[p] = f32x2 over batches (2p, 2p+1).
__device__ __forceinline__ void mv_slab(const float* __restrict__ Ws,
                                        const float* __restrict__ hf,
                                        int kbase, int lc,
                                        unsigned long long acc[4]) {
    const float* w = Ws + kbase * 128 + lc;
    const float* h = hf + kbase * 8;
    #pragma unroll 8
    for (int k = 0; k < 64; ++k) {
        float wv = w[k * 128];
        unsigned long long wd = pack2(wv, wv);
        ulonglong2 hA = *reinterpret_cast<const ulonglong2*>(h + k * 8);      // b0..b3
        ulonglong2 hB = *reinterpret_cast<const ulonglong2*>(h + k * 8 + 4);  // b4..b7
        fma2p(acc[0], wd, hA.x);
        fma2p(acc[1], wd, hA.y);
        fma2p(acc[2], wd, hB.x);
        fma2p(acc[3], wd, hB.y);
    }
}

__device__ __forceinline__ void plstm_gate2(float zi, float zf, float zg, float zo,
                                            float tcur, float tau, float s,
                                            float& h, float& c) {
    float ch = sigmoidf_(zf) * c + sigmoidf_(zi) * tanhf(zg);
    float hh = sigmoidf_(zo) * tanhf(ch);
    float d = tcur - s;
    float m = fmodf(d, tau);
    if (m < 0.0f) m += tau;           // python-style mod (divisor > 0)
    float phi = m / tau;
    float kg;
    if (phi < 0.5f * R_ON_)      kg = 2.0f * phi / R_ON_;
    else if (phi < R_ON_)        kg = 2.0f - 2.0f * phi / R_ON_;
    else                         kg = ALPHA_ * phi;
    h = kg * hh + (1.0f - kg) * h;
    c = kg * ch + (1.0f - kg) * c;
}

__global__ void __launch_bounds__(NTHR, 1) __cluster_dims__(CSZ, 1, 1)
plstm_cluster_kernel(const float* __restrict__ inputs, const float* __restrict__ times,
                     const float* __restrict__ gWx0, const float* __restrict__ gWh0,
                     const float* __restrict__ gb0,  const float* __restrict__ gtau0,
                     const float* __restrict__ gs0,  const float* __restrict__ gWx1,
                     const float* __restrict__ gWh1, const float* __restrict__ gb1,
                     const float* __restrict__ gtau1,const float* __restrict__ gs1,
                     const float* __restrict__ ggamma,const float* __restrict__ gbeta,
                     const float* __restrict__ gWfc, const float* __restrict__ gbfc,
                     float* __restrict__ out) {
    extern __shared__ float smraw[];
    SM& sm = *reinterpret_cast<SM*>(smraw);
    const int tid = threadIdx.x;
    uint32_t rank;
    asm("mov.u32 %0, %%cluster_ctarank;" : "=r"(rank));
    const int bstart = (blockIdx.x >> 2) * GC;

    const int ks    = tid >> 7;         // K slab (64 rows)
    const int lc    = tid & 127;        // own column
    const int kbase = ks << 6;
    const int gb    = tid >> 5;         // gate warp = batch
    const int gj    = tid & 31;         // own unit within warp

    // ---- one-time SMEM setup: this CTA's column slabs (gate-interleaved) ----
    for (int i = tid; i < 128 * 128; i += NTHR) {
        int k = i >> 7, c = i & 127;
        int gcol = ((c >> 5) << 7) + ((int)rank << 5) + (c & 31);
        sm.Wh0s[i] = gWh0[k * 512 + gcol];
        sm.Wx1g[i] = gWx1[k * 512 + gcol];   // raw; scaled by gamma below
        sm.Wh1s[i] = gWh1[k * 512 + gcol];
    }
    for (int i = tid; i < NF * 128; i += NTHR) {
        int f = i >> 7, c = i & 127;
        int gcol = ((c >> 5) << 7) + ((int)rank << 5) + (c & 31);
        sm.Wx0s[i] = gWx0[f * 512 + gcol];
    }
    for (int c = tid; c < 128; c += NTHR) {
        int gcol = ((c >> 5) << 7) + ((int)rank << 5) + (c & 31);
        sm.b0s[c] = gb0[gcol];
        sm.b1s[c] = gb1[gcol];
        sm.gmf[c] = ggamma[c];
        sm.btf[c] = gbeta[c];
    }
    if (tid < OWN) {
        int u = (int)rank * OWN + tid;
        sm.tau0s[tid] = gtau0[u]; sm.s0s[tid] = gs0[u];
        sm.tau1s[tid] = gtau1[u]; sm.s1s[tid] = gs1[u];
    }
    for (int i = tid; i < OWN * NC + 32; i += NTHR)
        sm.Wfcs[i] = (i < OWN * NC) ? gWfc[((int)rank * OWN + i / NC) * NC + (i % NC)] : 0.0f;
    if (tid < NC) sm.bfcs[tid] = gbfc[tid];
    for (int i = tid; i < 128 * 8; i += NTHR) {
        sm.h0f[0][i] = 0.0f; sm.h0f[1][i] = 0.0f;
        sm.h1f[0][i] = 0.0f; sm.h1f[1][i] = 0.0f;
    }
    sm.c0l[tid] = 0.0f; sm.c1l[tid] = 0.0f;
    if (tid < GC) {
        sm.tmb[0][tid] = times[(size_t)(bstart + tid) * TT];
        sm.tmb[1][tid] = times[(size_t)(bstart + tid) * TT + 1];
    }
    if (tid < GC * NF) {
        int g = tid / NF, f = tid - g * NF;
        sm.xb[0][g][f] = inputs[((size_t)(bstart + g) * TT) * NF + f];
        sm.xb[1][g][f] = inputs[((size_t)(bstart + g) * TT + 1) * NF + f];
    }
    __syncthreads();

    // ---- precompute: Wx1g *= gamma[k]; per-slab col sums S1 (Wx1*gm), S2 (Wx1*bt) ----
    {
        float s1 = 0.0f, s2 = 0.0f;
        for (int k = 0; k < 64; ++k) {
            int kk = kbase + k;
            float w = sm.Wx1g[kk * 128 + lc];
            float wg = w * sm.gmf[kk];
            sm.Wx1g[kk * 128 + lc] = wg;
            s1 += wg;
            s2 += w * sm.btf[kk];
        }
        sm.S1cs[ks][lc] = s1;
        sm.S2cs[ks][lc] = s2;
    }
    __syncthreads();

    // ---- pre-loop: z0(0) = x(0)@Wx0 + h0(=0)@Wh0 + b0 ----
    {
        unsigned long long acc[4];
        if (ks == 0) {
            float w0 = sm.Wx0s[lc], w1 = sm.Wx0s[128 + lc], w2 = sm.Wx0s[256 + lc];
            float bz = sm.b0s[lc];
            #pragma unroll
            for (int p = 0; p < 4; ++p) {
                const float* xl = sm.xb[0][2 * p];
                const float* xh = sm.xb[0][2 * p + 1];
                acc[p] = pack2(bz + xl[0] * w0 + xl[1] * w1 + xl[2] * w2,
                               bz + xh[0] * w0 + xh[1] * w1 + xh[2] * w2);
            }
        } else {
            #pragma unroll
            for (int p = 0; p < 4; ++p) acc[p] = 0ull;
        }
        mv_slab(sm.Wh0s, sm.h0f[0], kbase, lc, acc);
        #pragma unroll
        for (int p = 0; p < 4; ++p) {
            float2 v = unpack2(acc[p]);
            sm.z[(ks * 8 + 2 * p) * 128 + lc]     = v.x;
            sm.z[(ks * 8 + 2 * p + 1) * 128 + lc] = v.y;
        }
    }
    CLUSTER_SYNC();   // all CTAs initialized before any remote traffic

    for (int t = 0; t < TT; ++t) {
        const int par = t & 1, parn = par ^ 1;
        __syncthreads();                       // B1: z0 ready (pre-loop or tail of t-1)

        // ===== gates layer 0 (own units, all 8 warps) + h0 exchange + LN partials =====
        {
            const float* zb = sm.z + gb * 128;
            float zi = zb[gj]      + zb[1024 + gj];
            float zf = zb[32 + gj] + zb[1024 + 32 + gj];
            float zg = zb[64 + gj] + zb[1024 + 64 + gj];
            float zo = zb[96 + gj] + zb[1024 + 96 + gj];
            int u = (int)rank * OWN + gj;
            float h = sm.h0f[par][u * 8 + gb];
            float c = sm.c0l[gb * OWN + gj];
            plstm_gate2(zi, zf, zg, zo, sm.tmb[par][gb], sm.tau0s[gj], sm.s0s[gj], h, c);
            sm.c0l[gb * OWN + gj] = c;
            bcast4_f32(&sm.h0f[parn][u * 8 + gb], h);
            float s = h, q = h * h;
            #pragma unroll
            for (int o = 16; o; o >>= 1) {
                s += __shfl_xor_sync(0xffffffffu, s, o);
                q += __shfl_xor_sync(0xffffffffu, q, o);
            }
            if (gj == 0) {
                bcast4_f32(&sm.red_s[rank * GC + gb], s);
                bcast4_f32(&sm.red_q[rank * GC + gb], q);
            }
        }
        CLUSTER_ARRIVE();                      // S1 arrive

        // ===== overlap S1: pre-fold z1 += Wh1 @ h1(t-1) + b1 + S2c (register acc) =====
        unsigned long long accW[4];
        {
            float c0 = sm.S2cs[ks][lc] + (ks == 0 ? sm.b1s[lc] : 0.0f);
            #pragma unroll
            for (int p = 0; p < 4; ++p) accW[p] = pack2(c0, c0);
            mv_slab(sm.Wh1s, sm.h1f[par], kbase, lc, accW);
        }
        CLUSTER_WAIT();                        // S1 wait: h0f[parn] + LN partials visible

        // ===== z1 finish: A = Wx1g @ h0, apply LN fold, store z =====
        {
            unsigned long long A[4];
            #pragma unroll
            for (int p = 0; p < 4; ++p) A[p] = 0ull;
            mv_slab(sm.Wx1g, sm.h0f[parn], kbase, lc, A);
            // lane-parallel LN stats (batch = lane&7), then shfl-broadcast
            int bl = gj & 7;
            float s4 = sm.red_s[bl] + sm.red_s[8 + bl] + sm.red_s[16 + bl] + sm.red_s[24 + bl];
            float q4 = sm.red_q[bl] + sm.red_q[8 + bl] + sm.red_q[16 + bl] + sm.red_q[24 + bl];
            float mu  = s4 * (1.0f / 128.0f);
            float var = fmaxf(q4 * (1.0f / 128.0f) - mu * mu, 0.0f);
            float rs  = rsqrtf(var + LN_EPS_);
            float rm  = rs * mu;
            float rsv[8], rmv[8];
            #pragma unroll
            for (int b = 0; b < 8; ++b) {
                rsv[b] = __shfl_sync(0xffffffffu, rs, b);
                rmv[b] = __shfl_sync(0xffffffffu, rm, b);
            }
            float S1 = sm.S1cs[ks][lc];
            #pragma unroll
            for (int p = 0; p < 4; ++p) {
                float2 a = unpack2(A[p]);
                float2 w = unpack2(accW[p]);
                sm.z[(ks * 8 + 2 * p) * 128 + lc]     = w.x + rsv[2 * p] * a.x     - rmv[2 * p] * S1;
                sm.z[(ks * 8 + 2 * p + 1) * 128 + lc] = w.y + rsv[2 * p + 1] * a.y - rmv[2 * p + 1] * S1;
            }
        }
        __syncthreads();                       // B3: z1 ready

        // ===== gates layer 1 (own units) + h1 exchange + in-warp FC partials =====
        {
            const float* zb = sm.z + gb * 128;
            float zi = zb[gj]      + zb[1024 + gj];
            float zf = zb[32 + gj] + zb[1024 + 32 + gj];
            float zg = zb[64 + gj] + zb[1024 + 64 + gj];
            float zo = zb[96 + gj] + zb[1024 + 96 + gj];
            int u = (int)rank * OWN + gj;
            float h = sm.h1f[par][u * 8 + gb];
            float c = sm.c1l[gb * OWN + gj];
            plstm_gate2(zi, zf, zg, zo, sm.tmb[par][gb], sm.tau1s[gj], sm.s1s[gj], h, c);
            sm.c1l[gb * OWN + gj] = c;
            bcast4_f32(&sm.h1f[parn][u * 8 + gb], h);
            // FC partial over this warp's 32 own units; lane = class (lanes 10-31 dummy)
            float a = 0.0f;
            #pragma unroll
            for (int j = 0; j < OWN; ++j)
                a += __shfl_sync(0xffffffffu, h, j) * sm.Wfcs[j * NC + gj];
            if (gj < NC) {
                int owner = gb >> 1, bL = gb & 1;
                uint32_t ad = (uint32_t)__cvta_generic_to_shared(
                    &sm.lrecv[((int)rank * 2 + bL) * 16 + gj]);
                st_cluster_f32(ad, (uint32_t)owner, a);
            }
        }
        __syncthreads();                       // B4: gates1 z-reads done
        CLUSTER_ARRIVE();                      // S2 arrive

        // ===== overlap S2: next step's layer-0 matvec + x/t prefetch =====
        if (t + 1 < TT) {
            unsigned long long acc[4];
            if (ks == 0) {
                float w0 = sm.Wx0s[lc], w1 = sm.Wx0s[128 + lc], w2 = sm.Wx0s[256 + lc];
                float bz = sm.b0s[lc];
                #pragma unroll
                for (int p = 0; p < 4; ++p) {
                    const float* xl = sm.xb[parn][2 * p];
                    const float* xh = sm.xb[parn][2 * p + 1];
                    acc[p] = pack2(bz + xl[0] * w0 + xl[1] * w1 + xl[2] * w2,
                                   bz + xh[0] * w0 + xh[1] * w1 + xh[2] * w2);
                }
            } else {
                #pragma unroll
                for (int p = 0; p < 4; ++p) acc[p] = 0ull;
            }
            mv_slab(sm.Wh0s, sm.h0f[parn], kbase, lc, acc);   // h0(t), synced at S1
            #pragma unroll
            for (int p = 0; p < 4; ++p) {
                float2 v = unpack2(acc[p]);
                sm.z[(ks * 8 + 2 * p) * 128 + lc]     = v.x;
                sm.z[(ks * 8 + 2 * p + 1) * 128 + lc] = v.y;
            }
            if (t + 2 < TT) {
                if (tid < GC)
                    sm.tmb[par][tid] = times[(size_t)(bstart + tid) * TT + t + 2];
                if (tid < GC * NF) {
                    int g = tid / NF, f = tid - g * NF;
                    sm.xb[par][g][f] = inputs[((size_t)(bstart + g) * TT + t + 2) * NF + f];
                }
            }
        }
        CLUSTER_WAIT();                        // S2 wait: h1f[parn] + logit partials visible

        // ===== softmax + output for this CTA's 2 batches =====
        if (tid < 2) {
            float lg[NC], mx = -1e30f;
            #pragma unroll
            for (int c2 = 0; c2 < NC; ++c2) {
                float v = sm.bfcs[c2]
                        + sm.lrecv[(0 + tid) * 16 + c2] + sm.lrecv[(2 + tid) * 16 + c2]
                        + sm.lrecv[(4 + tid) * 16 + c2] + sm.lrecv[(6 + tid) * 16 + c2];
                lg[c2] = v; mx = fmaxf(mx, v);
            }
            float e[NC], ssum = 0.0f;
            #pragma unroll
            for (int c2 = 0; c2 < NC; ++c2) { e[c2] = expf(lg[c2] - mx); ssum += e[c2]; }
            float inv = 1.0f / ssum;
            float* op = out + ((size_t)(bstart + (int)rank * 2 + tid) * TT + t) * NC;
            #pragma unroll
            for (int c2 = 0; c2 < NC; ++c2) op[c2] = e[c2] * inv;
        }
    }
}

extern "C" void kernel_launch(void* const* d_in, const int* in_sizes, int n_in,
                              void* d_out, int out_size) {
    const float* inputs = (const float*)d_in[0];
    const float* times  = (const float*)d_in[1];
    const float* Wx0    = (const float*)d_in[2];
    const float* Wh0    = (const float*)d_in[3];
    const float* b0     = (const float*)d_in[4];
    const float* tau0   = (const float*)d_in[5];
    const float* s0     = (const float*)d_in[6];
    const float* Wx1    = (const float*)d_in[7];
    const float* Wh1    = (const float*)d_in[8];
    const float* b1     = (const float*)d_in[9];
    const float* tau1   = (const float*)d_in[10];
    const float* s1     = (const float*)d_in[11];
    const float* gamma  = (const float*)d_in[12];
    const float* beta   = (const float*)d_in[13];
    const float* Wfc    = (const float*)d_in[14];
    const float* bfc    = (const float*)d_in[15];

    cudaFuncSetAttribute(plstm_cluster_kernel,
                         cudaFuncAttributeMaxDynamicSharedMemorySize,
                         (int)sizeof(SM));
    plstm_cluster_kernel<<<NCTA, NTHR, sizeof(SM)>>>(
        inputs, times, Wx0, Wh0, b0, tau0, s0,
        Wx1, Wh1, b1, tau1, s1, gamma, beta, Wfc, bfc, (float*)d_out);
}

// round 10
// speedup vs baseline: 1.2493x; 1.0611x over previous
#include <cuda_runtime.h>
#include <math.h>
#include <stdint.h>

// Problem constants
#define U      128
#define NC     10
#define NF     3
#define TT     1000
#define BB     256
#define CSZ    4              // CTAs per cluster
#define GC     8              // batch elements per cluster
#define OWN    32             // units owned per CTA
#define NTHR   256
#define NCTA   128            // (BB/GC)*CSZ

#define R_ON_   0.05f
#define ALPHA_  0.001f
#define LN_EPS_ 1e-3f

// interleaved weight index: [k/4][lc][4]
#define WNI(k, c) (((((k) >> 2) * 128 + (c)) << 2) + ((k) & 3))

// ---- packed f32x2 helpers (FFMA2: 2x fp32 MAC throughput) ----
__device__ __forceinline__ unsigned long long pack2(float a, float b) {
    unsigned long long r;
    asm("mov.b64 %0, {%1, %2};" : "=l"(r) : "f"(a), "f"(b));
    return r;
}
__device__ __forceinline__ float2 unpack2(unsigned long long v) {
    float2 r;
    asm("mov.b64 {%0, %1}, %2;" : "=f"(r.x), "=f"(r.y) : "l"(v));
    return r;
}
__device__ __forceinline__ void fma2p(unsigned long long& acc,
                                      unsigned long long a,
                                      unsigned long long b) {
    asm("fma.rn.f32x2 %0, %1, %2, %0;" : "+l"(acc) : "l"(a), "l"(b));
}

// ---- fast transcendental helpers (rel err ~1e-6, budget is 1e-3) ----
__device__ __forceinline__ float fsig(float x) {
    return __fdividef(1.0f, 1.0f + __expf(-x));
}
__device__ __forceinline__ float ftanh(float x) {
    float ax = fabsf(x);
    float e  = __expf(-2.0f * ax);
    float t  = __fdividef(1.0f - e, 1.0f + e);
    return copysignf(t, x);
}

#define CLUSTER_ARRIVE() asm volatile("barrier.cluster.arrive.aligned;" ::: "memory")
#define CLUSTER_WAIT()   asm volatile("barrier.cluster.wait.aligned;"   ::: "memory")
#define CLUSTER_SYNC()   do { CLUSTER_ARRIVE(); CLUSTER_WAIT(); } while (0)

__device__ __forceinline__ void st_cluster_f32(uint32_t laddr, uint32_t r, float v) {
    uint32_t ra;
    asm volatile("mapa.shared::cluster.u32 %0, %1, %2;" : "=r"(ra) : "r"(laddr), "r"(r));
    asm volatile("st.shared::cluster.f32 [%0], %1;" :: "r"(ra), "f"(v) : "memory");
}
// store v to the same SMEM slot in all 4 cluster CTAs (incl. self)
__device__ __forceinline__ void bcast4_f32(void* p, float v) {
    uint32_t a = (uint32_t)__cvta_generic_to_shared(p);
    #pragma unroll
    for (uint32_t r = 0; r < CSZ; ++r) st_cluster_f32(a, r, v);
}

// Dynamic SMEM: ~232.2 KB (<= 232448 B limit, 1 CTA/SM)
struct __align__(16) SM {
    float Wh0s[128 * 128];      // own 128 cols (gate-interleaved) of Wh0, [k/4][lc][4]
    float Wx1g[128 * 128];      // own cols of Wx1 * gamma[k], same layout
    float Wh1s[128 * 128];
    float z[2 * 8 * 128];       // [ks][b][lc] gate pre-activation partials
    float h0f[2][128 * 8];      // full h0, [unit][b], double-buffered by t-parity
    float h1f[2][128 * 8];
    float c0l[GC * OWN], c1l[GC * OWN];  // own-unit cell state [b][j]
    float Wx0s[NF * 128];       // own cols of Wx0 [f][lc]
    float b0s[128], b1s[128];   // own cols of biases
    float S1cs[2][128];         // per-slab col sums of Wx1g
    float S2cs[2][128];         // per-slab col sums of Wx1*beta
    float tau0s[OWN], s0s[OWN], tau1s[OWN], s1s[OWN];
    float itau0s[OWN], itau1s[OWN];      // 1/tau
    float gmf[128], btf[128];   // full gamma/beta (precompute only)
    float Wfcs[OWN * NC + 32];  // own rows of Wfc (padded for OOB-safe reads)
    float bfcs[16];
    float red_s[CSZ * GC], red_q[CSZ * GC];   // LN partials [srcRank][b]
    float lrecv[CSZ * 2 * 16];  // logit partials [srcRank][localBatch][c pad16]
    float xb[2][GC][4];         // double-buffered inputs (f padded to 4)
    float tmb[2][GC];           // double-buffered times
};

// One 64-row K-slab of  hf[128 units][8 b]  @  Ws[128][128 own cols], 1 col/thread.
// Ws layout [k/4][lc][4]; acc[p] = f32x2 over batches (2p, 2p+1).
__device__ __forceinline__ void mv_slab(const float* __restrict__ Ws,
                                        const float* __restrict__ hf,
                                        int kbase, int lc,
                                        unsigned long long acc[4]) {
    const float4* w4 = reinterpret_cast<const float4*>(Ws) + ((kbase >> 2) * 128 + lc);
    const float* h = hf + kbase * 8;
    #pragma unroll 4
    for (int k4 = 0; k4 < 16; ++k4) {
        float4 w = w4[k4 * 128];
        const float* hh = h + k4 * 32;
        float wv[4] = {w.x, w.y, w.z, w.w};
        #pragma unroll
        for (int j = 0; j < 4; ++j) {
            unsigned long long wd = pack2(wv[j], wv[j]);
            ulonglong2 hA = *reinterpret_cast<const ulonglong2*>(hh + j * 8);      // b0..b3
            ulonglong2 hB = *reinterpret_cast<const ulonglong2*>(hh + j * 8 + 4);  // b4..b7
            fma2p(acc[0], wd, hA.x);
            fma2p(acc[1], wd, hA.y);
            fma2p(acc[2], wd, hB.x);
            fma2p(acc[3], wd, hB.y);
        }
    }
}

// PhasedLSTM gate + time gate. Fast exact-ish mod: q = trunc(d/tau) via
// reciprocal (q < 1000 << 2^24, off-by-one fixed by clamps); m = fma(-q,tau,d)
// is single-rounded, so wrap decisions match exact fmod to ~1 ulp.
__device__ __forceinline__ void plstm_gate2(float zi, float zf, float zg, float zo,
                                            float tcur, float tau, float itau, float s,
                                            float& h, float& c) {
    float ch = fsig(zf) * c + fsig(zi) * ftanh(zg);
    float hh = fsig(zo) * ftanh(ch);
    float d = tcur - s;
    float q = truncf(d * itau);
    float m = fmaf(-q, tau, d);
    m = (m < 0.0f)  ? m + tau : m;
    m = (m >= tau)  ? m - tau : m;
    m = (m < 0.0f)  ? m + tau : m;
    float phi = m * itau;
    float kg;
    if (phi < 0.5f * R_ON_)      kg = (2.0f * phi) / R_ON_;
    else if (phi < R_ON_)        kg = 2.0f - (2.0f * phi) / R_ON_;
    else                         kg = ALPHA_ * phi;
    h = kg * hh + (1.0f - kg) * h;
    c = kg * ch + (1.0f - kg) * c;
}

__global__ void __launch_bounds__(NTHR, 1) __cluster_dims__(CSZ, 1, 1)
plstm_cluster_kernel(const float* __restrict__ inputs, const float* __restrict__ times,
                     const float* __restrict__ gWx0, const float* __restrict__ gWh0,
                     const float* __restrict__ gb0,  const float* __restrict__ gtau0,
                     const float* __restrict__ gs0,  const float* __restrict__ gWx1,
                     const float* __restrict__ gWh1, const float* __restrict__ gb1,
                     const float* __restrict__ gtau1,const float* __restrict__ gs1,
                     const float* __restrict__ ggamma,const float* __restrict__ gbeta,
                     const float* __restrict__ gWfc, const float* __restrict__ gbfc,
                     float* __restrict__ out) {
    extern __shared__ float smraw[];
    SM& sm = *reinterpret_cast<SM*>(smraw);
    const int tid = threadIdx.x;
    uint32_t rank;
    asm("mov.u32 %0, %%cluster_ctarank;" : "=r"(rank));
    const int bstart = (blockIdx.x >> 2) * GC;

    const int ks    = tid >> 7;         // K slab (64 rows)
    const int lc    = tid & 127;        // own column
    const int kbase = ks << 6;
    const int gb    = tid >> 5;         // gate warp = batch
    const int gj    = tid & 31;         // own unit within warp

    // ---- one-time SMEM setup: this CTA's column slabs (gate-interleaved) ----
    for (int i = tid; i < 128 * 128; i += NTHR) {
        int k = i >> 7, c = i & 127;
        int gcol = ((c >> 5) << 7) + ((int)rank << 5) + (c & 31);
        int ni = WNI(k, c);
        sm.Wh0s[ni] = gWh0[k * 512 + gcol];
        sm.Wx1g[ni] = gWx1[k * 512 + gcol];   // raw; scaled by gamma below
        sm.Wh1s[ni] = gWh1[k * 512 + gcol];
    }
    for (int i = tid; i < NF * 128; i += NTHR) {
        int f = i >> 7, c = i & 127;
        int gcol = ((c >> 5) << 7) + ((int)rank << 5) + (c & 31);
        sm.Wx0s[i] = gWx0[f * 512 + gcol];
    }
    for (int c = tid; c < 128; c += NTHR) {
        int gcol = ((c >> 5) << 7) + ((int)rank << 5) + (c & 31);
        sm.b0s[c] = gb0[gcol];
        sm.b1s[c] = gb1[gcol];
        sm.gmf[c] = ggamma[c];
        sm.btf[c] = gbeta[c];
    }
    if (tid < OWN) {
        int u = (int)rank * OWN + tid;
        float t0 = gtau0[u], t1 = gtau1[u];
        sm.tau0s[tid] = t0; sm.s0s[tid] = gs0[u]; sm.itau0s[tid] = 1.0f / t0;
        sm.tau1s[tid] = t1; sm.s1s[tid] = gs1[u]; sm.itau1s[tid] = 1.0f / t1;
    }
    for (int i = tid; i < OWN * NC + 32; i += NTHR)
        sm.Wfcs[i] = (i < OWN * NC) ? gWfc[((int)rank * OWN + i / NC) * NC + (i % NC)] : 0.0f;
    if (tid < NC) sm.bfcs[tid] = gbfc[tid];
    for (int i = tid; i < 128 * 8; i += NTHR) {
        sm.h0f[0][i] = 0.0f; sm.h0f[1][i] = 0.0f;
        sm.h1f[0][i] = 0.0f; sm.h1f[1][i] = 0.0f;
    }
    sm.c0l[tid] = 0.0f; sm.c1l[tid] = 0.0f;
    if (tid < GC) {
        sm.tmb[0][tid] = times[(size_t)(bstart + tid) * TT];
        sm.tmb[1][tid] = times[(size_t)(bstart + tid) * TT + 1];
    }
    if (tid < GC * NF) {
        int g = tid / NF, f = tid - g * NF;
        sm.xb[0][g][f] = inputs[((size_t)(bstart + g) * TT) * NF + f];
        sm.xb[1][g][f] = inputs[((size_t)(bstart + g) * TT + 1) * NF + f];
    }
    __syncthreads();

    // ---- precompute: Wx1g *= gamma[k]; per-slab col sums S1 (Wx1*gm), S2 (Wx1*bt) ----
    {
        float s1 = 0.0f, s2 = 0.0f;
        for (int k = 0; k < 64; ++k) {
            int kk = kbase + k;
            int ni = WNI(kk, lc);
            float w = sm.Wx1g[ni];
            float wg = w * sm.gmf[kk];
            sm.Wx1g[ni] = wg;
            s1 += wg;
            s2 += w * sm.btf[kk];
        }
        sm.S1cs[ks][lc] = s1;
        sm.S2cs[ks][lc] = s2;
    }
    __syncthreads();

    // ---- pre-loop: z0(0) = x(0)@Wx0 + h0(=0)@Wh0 + b0 ----
    {
        unsigned long long acc[4];
        if (ks == 0) {
            float w0 = sm.Wx0s[lc], w1 = sm.Wx0s[128 + lc], w2 = sm.Wx0s[256 + lc];
            float bz = sm.b0s[lc];
            #pragma unroll
            for (int p = 0; p < 4; ++p) {
                const float* xl = sm.xb[0][2 * p];
                const float* xh = sm.xb[0][2 * p + 1];
                acc[p] = pack2(bz + xl[0] * w0 + xl[1] * w1 + xl[2] * w2,
                               bz + xh[0] * w0 + xh[1] * w1 + xh[2] * w2);
            }
        } else {
            #pragma unroll
            for (int p = 0; p < 4; ++p) acc[p] = 0ull;
        }
        mv_slab(sm.Wh0s, sm.h0f[0], kbase, lc, acc);
        #pragma unroll
        for (int p = 0; p < 4; ++p) {
            float2 v = unpack2(acc[p]);
            sm.z[(ks * 8 + 2 * p) * 128 + lc]     = v.x;
            sm.z[(ks * 8 + 2 * p + 1) * 128 + lc] = v.y;
        }
    }
    CLUSTER_SYNC();   // all CTAs initialized before any remote traffic

    for (int t = 0; t < TT; ++t) {
        const int par = t & 1, parn = par ^ 1;
        __syncthreads();                       // B1: z0 ready (pre-loop or tail of t-1)

        // ===== gates layer 0 (own units, all 8 warps) + h0 exchange + LN partials =====
        {
            const float* zb = sm.z + gb * 128;
            float zi = zb[gj]      + zb[1024 + gj];
            float zf = zb[32 + gj] + zb[1024 + 32 + gj];
            float zg = zb[64 + gj] + zb[1024 + 64 + gj];
            float zo = zb[96 + gj] + zb[1024 + 96 + gj];
            int u = (int)rank * OWN + gj;
            float h = sm.h0f[par][u * 8 + gb];
            float c = sm.c0l[gb * OWN + gj];
            plstm_gate2(zi, zf, zg, zo, sm.tmb[par][gb],
                        sm.tau0s[gj], sm.itau0s[gj], sm.s0s[gj], h, c);
            sm.c0l[gb * OWN + gj] = c;
            bcast4_f32(&sm.h0f[parn][u * 8 + gb], h);
            float s = h, q = h * h;
            #pragma unroll
            for (int o = 16; o; o >>= 1) {
                s += __shfl_xor_sync(0xffffffffu, s, o);
                q += __shfl_xor_sync(0xffffffffu, q, o);
            }
            if (gj == 0) {
                bcast4_f32(&sm.red_s[rank * GC + gb], s);
                bcast4_f32(&sm.red_q[rank * GC + gb], q);
            }
        }
        CLUSTER_ARRIVE();                      // S1 arrive

        // ===== overlap S1: pre-fold z1 += Wh1 @ h1(t-1) + b1 + S2c (register acc) =====
        unsigned long long accW[4];
        {
            float c0 = sm.S2cs[ks][lc] + (ks == 0 ? sm.b1s[lc] : 0.0f);
            #pragma unroll
            for (int p = 0; p < 4; ++p) accW[p] = pack2(c0, c0);
            mv_slab(sm.Wh1s, sm.h1f[par], kbase, lc, accW);
        }
        CLUSTER_WAIT();                        // S1 wait: h0f[parn] + LN partials visible

        // ===== z1 finish: A = Wx1g @ h0, apply LN fold, store z =====
        {
            unsigned long long A[4];
            #pragma unroll
            for (int p = 0; p < 4; ++p) A[p] = 0ull;
            mv_slab(sm.Wx1g, sm.h0f[parn], kbase, lc, A);
            // lane-parallel LN stats (batch = lane&7), then shfl-broadcast
            int bl = gj & 7;
            float s4 = sm.red_s[bl] + sm.red_s[8 + bl] + sm.red_s[16 + bl] + sm.red_s[24 + bl];
            float q4 = sm.red_q[bl] + sm.red_q[8 + bl] + sm.red_q[16 + bl] + sm.red_q[24 + bl];
            float mu  = s4 * (1.0f / 128.0f);
            float var = fmaxf(q4 * (1.0f / 128.0f) - mu * mu, 0.0f);
            float rs  = rsqrtf(var + LN_EPS_);
            float rm  = rs * mu;
            float rsv[8], rmv[8];
            #pragma unroll
            for (int b = 0; b < 8; ++b) {
                rsv[b] = __shfl_sync(0xffffffffu, rs, b);
                rmv[b] = __shfl_sync(0xffffffffu, rm, b);
            }
            float S1 = sm.S1cs[ks][lc];
            #pragma unroll
            for (int p = 0; p < 4; ++p) {
                float2 a = unpack2(A[p]);
                float2 w = unpack2(accW[p]);
                sm.z[(ks * 8 + 2 * p) * 128 + lc]     = w.x + rsv[2 * p] * a.x     - rmv[2 * p] * S1;
                sm.z[(ks * 8 + 2 * p + 1) * 128 + lc] = w.y + rsv[2 * p + 1] * a.y - rmv[2 * p + 1] * S1;
            }
        }
        __syncthreads();                       // B3: z1 ready

        // ===== gates layer 1 (own units) + h1 exchange + in-warp FC partials =====
        {
            const float* zb = sm.z + gb * 128;
            float zi = zb[gj]      + zb[1024 + gj];
            float zf = zb[32 + gj] + zb[1024 + 32 + gj];
            float zg = zb[64 + gj] + zb[1024 + 64 + gj];
            float zo = zb[96 + gj] + zb[1024 + 96 + gj];
            int u = (int)rank * OWN + gj;
            float h = sm.h1f[par][u * 8 + gb];
            float c = sm.c1l[gb * OWN + gj];
            plstm_gate2(zi, zf, zg, zo, sm.tmb[par][gb],
                        sm.tau1s[gj], sm.itau1s[gj], sm.s1s[gj], h, c);
            sm.c1l[gb * OWN + gj] = c;
            bcast4_f32(&sm.h1f[parn][u * 8 + gb], h);
            // FC partial over this warp's 32 own units; lane = class (lanes 10-31 dummy)
            float a = 0.0f;
            #pragma unroll
            for (int j = 0; j < OWN; ++j)
                a += __shfl_sync(0xffffffffu, h, j) * sm.Wfcs[j * NC + gj];
            if (gj < NC) {
                int owner = gb >> 1, bL = gb & 1;
                uint32_t ad = (uint32_t)__cvta_generic_to_shared(
                    &sm.lrecv[((int)rank * 2 + bL) * 16 + gj]);
                st_cluster_f32(ad, (uint32_t)owner, a);
            }
        }
        __syncthreads();                       // B4: gates1 z-reads done
        CLUSTER_ARRIVE();                      // S2 arrive

        // ===== overlap S2: next step's layer-0 matvec + x/t prefetch =====
        if (t + 1 < TT) {
            unsigned long long acc[4];
            if (ks == 0) {
                float w0 = sm.Wx0s[lc], w1 = sm.Wx0s[128 + lc], w2 = sm.Wx0s[256 + lc];
                float bz = sm.b0s[lc];
                #pragma unroll
                for (int p = 0; p < 4; ++p) {
                    const float* xl = sm.xb[parn][2 * p];
                    const float* xh = sm.xb[parn][2 * p + 1];
                    acc[p] = pack2(bz + xl[0] * w0 + xl[1] * w1 + xl[2] * w2,
                                   bz + xh[0] * w0 + xh[1] * w1 + xh[2] * w2);
                }
            } else {
                #pragma unroll
                for (int p = 0; p < 4; ++p) acc[p] = 0ull;
            }
            mv_slab(sm.Wh0s, sm.h0f[parn], kbase, lc, acc);   // h0(t), synced at S1
            #pragma unroll
            for (int p = 0; p < 4; ++p) {
                float2 v = unpack2(acc[p]);
                sm.z[(ks * 8 + 2 * p) * 128 + lc]     = v.x;
                sm.z[(ks * 8 + 2 * p + 1) * 128 + lc] = v.y;
            }
            if (t + 2 < TT) {
                if (tid < GC)
                    sm.tmb[par][tid] = times[(size_t)(bstart + tid) * TT + t + 2];
                if (tid < GC * NF) {
                    int g = tid / NF, f = tid - g * NF;
                    sm.xb[par][g][f] = inputs[((size_t)(bstart + g) * TT + t + 2) * NF + f];
                }
            }
        }
        CLUSTER_WAIT();                        // S2 wait: h1f[parn] + logit partials visible

        // ===== warp-parallel softmax + output for this CTA's 2 batches =====
        if (tid < 32) {
            int bL = tid & 1, c2 = tid >> 1;       // lanes 0-19 valid (2 batches x 10 classes)
            bool valid = (c2 < NC);
            float lg = -1e30f;
            if (valid)
                lg = sm.bfcs[c2]
                   + sm.lrecv[(0 + bL) * 16 + c2] + sm.lrecv[(2 + bL) * 16 + c2]
                   + sm.lrecv[(4 + bL) * 16 + c2] + sm.lrecv[(6 + bL) * 16 + c2];
            float mx = lg;
            #pragma unroll
            for (int o = 2; o < 32; o <<= 1)
                mx = fmaxf(mx, __shfl_xor_sync(0xffffffffu, mx, o));
            float e = valid ? __expf(lg - mx) : 0.0f;
            float ssum = e;
            #pragma unroll
            for (int o = 2; o < 32; o <<= 1)
                ssum += __shfl_xor_sync(0xffffffffu, ssum, o);
            if (valid)
                out[((size_t)(bstart + (int)rank * 2 + bL) * TT + t) * NC + c2]
                    = e * __fdividef(1.0f, ssum);
        }
    }
}

extern "C" void kernel_launch(void* const* d_in, const int* in_sizes, int n_in,
                              void* d_out, int out_size) {
    const float* inputs = (const float*)d_in[0];
    const float* times  = (const float*)d_in[1];
    const float* Wx0    = (const float*)d_in[2];
    const float* Wh0    = (const float*)d_in[3];
    const float* b0     = (const float*)d_in[4];
    const float* tau0   = (const float*)d_in[5];
    const float* s0     = (const float*)d_in[6];
    const float* Wx1    = (const float*)d_in[7];
    const float* Wh1    = (const float*)d_in[8];
    const float* b1     = (const float*)d_in[9];
    const float* tau1   = (const float*)d_in[10];
    const float* s1     = (const float*)d_in[11];
    const float* gamma  = (const float*)d_in[12];
    const float* beta   = (const float*)d_in[13];
    const float* Wfc    = (const float*)d_in[14];
    const float* bfc    = (const float*)d_in[15];

    cudaFuncSetAttribute(plstm_cluster_kernel,
                         cudaFuncAttributeMaxDynamicSharedMemorySize,
                         (int)sizeof(SM));
    plstm_cluster_kernel<<<NCTA, NTHR, sizeof(SM)>>>(
        inputs, times, Wx0, Wh0, b0, tau0, s0,
        Wx1, Wh1, b1, tau1, s1, gamma, beta, Wfc, bfc, (float*)d_out);
}

// round 11
// speedup vs baseline: 1.3666x; 1.0939x over previous
#include <cuda_runtime.h>
#include <math.h>
#include <stdint.h>

// Problem constants
#define U      128
#define NC     10
#define NF     3
#define TT     1000
#define BB     256
#define CSZ    4              // CTAs per cluster
#define GC     8              // batch elements per cluster
#define OWN    32             // units owned per CTA
#define NTHR   256
#define NCTA   128            // (BB/GC)*CSZ
#define RS     260            // hT row stride in floats (1040B, bank-skewed)

#define R_ON_   0.05f
#define ALPHA_  0.001f
#define LN_EPS_ 1e-3f

// ---- packed f32x2 helpers (FFMA2: 2x fp32 MAC throughput) ----
__device__ __forceinline__ unsigned long long pack2(float a, float b) {
    unsigned long long r;
    asm("mov.b64 %0, {%1, %2};" : "=l"(r) : "f"(a), "f"(b));
    return r;
}
__device__ __forceinline__ void fma2p(unsigned long long& acc,
                                      unsigned long long a,
                                      unsigned long long b) {
    asm("fma.rn.f32x2 %0, %1, %2, %0;" : "+l"(acc) : "l"(a), "l"(b));
}

// ---- fast transcendental helpers (rel err ~1e-6, budget is 1e-3) ----
__device__ __forceinline__ float fsig(float x) {
    return __fdividef(1.0f, 1.0f + __expf(-x));
}
__device__ __forceinline__ float ftanh(float x) {
    float ax = fabsf(x);
    float e  = __expf(-2.0f * ax);
    float t  = __fdividef(1.0f - e, 1.0f + e);
    return copysignf(t, x);
}

#define CLUSTER_ARRIVE() asm volatile("barrier.cluster.arrive.aligned;" ::: "memory")
#define CLUSTER_WAIT()   asm volatile("barrier.cluster.wait.aligned;"   ::: "memory")
#define CLUSTER_SYNC()   do { CLUSTER_ARRIVE(); CLUSTER_WAIT(); } while (0)

__device__ __forceinline__ void st_cluster_f32(uint32_t laddr, uint32_t r, float v) {
    uint32_t ra;
    asm volatile("mapa.shared::cluster.u32 %0, %1, %2;" : "=r"(ra) : "r"(laddr), "r"(r));
    asm volatile("st.shared::cluster.f32 [%0], %1;" :: "r"(ra), "f"(v) : "memory");
}
// store v to the same SMEM slot in all 4 cluster CTAs (incl. self)
__device__ __forceinline__ void bcast4_f32(void* p, float v) {
    uint32_t a = (uint32_t)__cvta_generic_to_shared(p);
    #pragma unroll
    for (uint32_t r = 0; r < CSZ; ++r) st_cluster_f32(a, r, v);
}

// Dynamic SMEM: 57856 floats = 231424 B (<= 232448 B limit, 1 CTA/SM)
struct __align__(16) SM {
    float Wh0s[128 * 128];      // own 128 cols (gate-interleaved) of Wh0, plain [k][lc]
    float Wx1g[128 * 128];      // own cols of Wx1 * gamma[k]
    float Wh1s[128 * 128];
    float z[2 * 8 * 128];       // [ks][b][lc] gate pre-activation partials
    float hT0[2][4 * RS];       // h0 transposed: [parity][bpair*RS + unit*2 + (b&1)]
    float hT1[2][4 * RS];       // h1, same layout
    float c0l[GC * OWN], c1l[GC * OWN];  // own-unit cell state [b][j]
    float Wx0s[NF * 128];       // own cols of Wx0 [f][lc]
    float b0s[128], b1s[128];   // own cols of biases
    float S1cs[2][128];         // per-slab col sums of Wx1g
    float S2cs[2][128];         // per-slab col sums of Wx1*beta
    float tau0s[OWN], s0s[OWN], itau0s[OWN];
    float tau1s[OWN], s1s[OWN], itau1s[OWN];
    float Wfcs[OWN * NC + 32];  // own rows of Wfc (padded for OOB-safe reads)
    float bfcs[16];
    float red_s[CSZ * GC], red_q[CSZ * GC];   // LN partials [srcRank][b]
    float lrecv[CSZ * 2 * 16];  // logit partials [srcRank][localBatch][c pad16]
    float xb[2][GC][4];         // double-buffered inputs (f padded to 4)
    float tmb[2][GC];           // double-buffered times
};

// One 64-row K-slab: 4 cols (quad) x 2 batches (bpair) per thread.
// Ws plain [k][128]; hbp = hT row for this bpair. acc[p][d]: f32x2 over
// cols (quad*4+2p, +1) for batch 2*bp+d.
__device__ __forceinline__ void mv2(const float* __restrict__ Ws,
                                    const float* __restrict__ hbp,
                                    int kbase, int quad,
                                    unsigned long long acc[2][2]) {
    const ulonglong2* w2 = reinterpret_cast<const ulonglong2*>(Ws + kbase * 128) + quad;
    const float4* h4 = reinterpret_cast<const float4*>(hbp) + (kbase >> 1);
    #pragma unroll 8
    for (int k2 = 0; k2 < 32; ++k2) {
        float4 h = h4[k2];                       // 2 k-steps x 2 batches
        ulonglong2 wA = w2[(2 * k2) * 32];       // k even: col-pairs
        ulonglong2 wB = w2[(2 * k2 + 1) * 32];   // k odd
        unsigned long long h00 = pack2(h.x, h.x);
        unsigned long long h01 = pack2(h.y, h.y);
        unsigned long long h10 = pack2(h.z, h.z);
        unsigned long long h11 = pack2(h.w, h.w);
        fma2p(acc[0][0], wA.x, h00); fma2p(acc[1][0], wA.y, h00);
        fma2p(acc[0][1], wA.x, h01); fma2p(acc[1][1], wA.y, h01);
        fma2p(acc[0][0], wB.x, h10); fma2p(acc[1][0], wB.y, h10);
        fma2p(acc[0][1], wB.x, h11); fma2p(acc[1][1], wB.y, h11);
    }
}

// PhasedLSTM gate + time gate (fast mod via reciprocal + clamps; q < 1000 << 2^24)
__device__ __forceinline__ void plstm_gate2(float zi, float zf, float zg, float zo,
                                            float tcur, float tau, float itau, float s,
                                            float& h, float& c) {
    float ch = fsig(zf) * c + fsig(zi) * ftanh(zg);
    float hh = fsig(zo) * ftanh(ch);
    float d = tcur - s;
    float q = truncf(d * itau);
    float m = fmaf(-q, tau, d);
    m = (m < 0.0f)  ? m + tau : m;
    m = (m >= tau)  ? m - tau : m;
    m = (m < 0.0f)  ? m + tau : m;
    float phi = m * itau;
    float kg;
    if (phi < 0.5f * R_ON_)      kg = (2.0f * phi) / R_ON_;
    else if (phi < R_ON_)        kg = 2.0f - (2.0f * phi) / R_ON_;
    else                         kg = ALPHA_ * phi;
    h = kg * hh + (1.0f - kg) * h;
    c = kg * ch + (1.0f - kg) * c;
}

__global__ void __launch_bounds__(NTHR, 1) __cluster_dims__(CSZ, 1, 1)
plstm_cluster_kernel(const float* __restrict__ inputs, const float* __restrict__ times,
                     const float* __restrict__ gWx0, const float* __restrict__ gWh0,
                     const float* __restrict__ gb0,  const float* __restrict__ gtau0,
                     const float* __restrict__ gs0,  const float* __restrict__ gWx1,
                     const float* __restrict__ gWh1, const float* __restrict__ gb1,
                     const float* __restrict__ gtau1,const float* __restrict__ gs1,
                     const float* __restrict__ ggamma,const float* __restrict__ gbeta,
                     const float* __restrict__ gWfc, const float* __restrict__ gbfc,
                     float* __restrict__ out) {
    extern __shared__ float smraw[];
    SM& sm = *reinterpret_cast<SM*>(smraw);
    const int tid = threadIdx.x;
    uint32_t rank;
    asm("mov.u32 %0, %%cluster_ctarank;" : "=r"(rank));
    const int bstart = (blockIdx.x >> 2) * GC;

    // matvec mapping: 256 threads = 2 ks-slabs x (8 quads x 4 bpairs per warp-of-slab)
    const int ks    = tid >> 7;
    const int lane  = tid & 31;
    const int wq    = (tid >> 5) & 3;
    const int bp    = lane >> 3;            // batch pair (batches 2bp, 2bp+1)
    const int quad  = wq * 8 + (lane & 7);  // column quad (cols quad*4 .. +3)
    const int kbase = ks << 6;
    const int lcq   = quad * 4;
    // gate mapping: warp gb = batch, lane gj = own unit
    const int gb = tid >> 5, gj = lane;
    const int gbp = gb >> 1, gdl = gb & 1;

    // ---- one-time SMEM setup: this CTA's column slabs (gate-interleaved cols) ----
    for (int i = tid; i < 128 * 128; i += NTHR) {
        int k = i >> 7, c = i & 127;
        int gcol = ((c >> 5) << 7) + ((int)rank << 5) + (c & 31);
        sm.Wh0s[i] = gWh0[k * 512 + gcol];
        sm.Wx1g[i] = gWx1[k * 512 + gcol];   // raw; scaled by gamma below
        sm.Wh1s[i] = gWh1[k * 512 + gcol];
    }
    for (int i = tid; i < NF * 128; i += NTHR) {
        int f = i >> 7, c = i & 127;
        int gcol = ((c >> 5) << 7) + ((int)rank << 5) + (c & 31);
        sm.Wx0s[i] = gWx0[f * 512 + gcol];
    }
    for (int c = tid; c < 128; c += NTHR) {
        int gcol = ((c >> 5) << 7) + ((int)rank << 5) + (c & 31);
        sm.b0s[c] = gb0[gcol];
        sm.b1s[c] = gb1[gcol];
    }
    if (tid < OWN) {
        int u = (int)rank * OWN + tid;
        float t0 = gtau0[u], t1 = gtau1[u];
        sm.tau0s[tid] = t0; sm.s0s[tid] = gs0[u]; sm.itau0s[tid] = 1.0f / t0;
        sm.tau1s[tid] = t1; sm.s1s[tid] = gs1[u]; sm.itau1s[tid] = 1.0f / t1;
    }
    for (int i = tid; i < OWN * NC + 32; i += NTHR)
        sm.Wfcs[i] = (i < OWN * NC) ? gWfc[((int)rank * OWN + i / NC) * NC + (i % NC)] : 0.0f;
    if (tid < NC) sm.bfcs[tid] = gbfc[tid];
    {
        float* p0 = &sm.hT0[0][0];
        float* p1 = &sm.hT1[0][0];
        for (int i = tid; i < 2 * 4 * RS; i += NTHR) { p0[i] = 0.0f; p1[i] = 0.0f; }
    }
    sm.c0l[tid] = 0.0f; sm.c1l[tid] = 0.0f;
    if (tid < GC) {
        sm.tmb[0][tid] = times[(size_t)(bstart + tid) * TT];
        sm.tmb[1][tid] = times[(size_t)(bstart + tid) * TT + 1];
    }
    if (tid < GC * NF) {
        int g = tid / NF, f = tid - g * NF;
        sm.xb[0][g][f] = inputs[((size_t)(bstart + g) * TT) * NF + f];
        sm.xb[1][g][f] = inputs[((size_t)(bstart + g) * TT + 1) * NF + f];
    }
    __syncthreads();

    // ---- precompute: Wx1g *= gamma[k]; per-slab col sums S1 (Wx1*gm), S2 (Wx1*bt) ----
    {
        const int lc = tid & 127;
        float s1 = 0.0f, s2 = 0.0f;
        for (int k = 0; k < 64; ++k) {
            int kk = kbase + k;
            int ni = kk * 128 + lc;
            float w = sm.Wx1g[ni];
            float gm = ggamma[kk], bt = gbeta[kk];
            float wg = w * gm;
            sm.Wx1g[ni] = wg;
            s1 += wg;
            s2 += w * bt;
        }
        sm.S1cs[ks][lc] = s1;
        sm.S2cs[ks][lc] = s2;
    }
    __syncthreads();

    // ---- pre-loop: z0(0) = x(0)@Wx0 + b0 (h0 = 0, so no matvec needed) ----
    {
        float* zp = sm.z + ks * 1024 + (2 * bp) * 128 + lcq;
        if (ks == 0) {
            float4 b0v = *reinterpret_cast<const float4*>(&sm.b0s[lcq]);
            float4 w0v = *reinterpret_cast<const float4*>(&sm.Wx0s[lcq]);
            float4 w1v = *reinterpret_cast<const float4*>(&sm.Wx0s[128 + lcq]);
            float4 w2v = *reinterpret_cast<const float4*>(&sm.Wx0s[256 + lcq]);
            #pragma unroll
            for (int d = 0; d < 2; ++d) {
                const float* x = sm.xb[0][2 * bp + d];
                float xa = x[0], xb_ = x[1], xc = x[2];
                zp[d * 128 + 0] = b0v.x + xa * w0v.x + xb_ * w1v.x + xc * w2v.x;
                zp[d * 128 + 1] = b0v.y + xa * w0v.y + xb_ * w1v.y + xc * w2v.y;
                zp[d * 128 + 2] = b0v.z + xa * w0v.z + xb_ * w1v.z + xc * w2v.z;
                zp[d * 128 + 3] = b0v.w + xa * w0v.w + xb_ * w1v.w + xc * w2v.w;
            }
        } else {
            #pragma unroll
            for (int d = 0; d < 2; ++d) {
                zp[d * 128 + 0] = 0.0f; zp[d * 128 + 1] = 0.0f;
                zp[d * 128 + 2] = 0.0f; zp[d * 128 + 3] = 0.0f;
            }
        }
    }
    CLUSTER_SYNC();   // all CTAs initialized before any remote traffic

    for (int t = 0; t < TT; ++t) {
        const int par = t & 1, parn = par ^ 1;
        __syncthreads();                       // B1: z0 ready (pre-loop or tail of t-1)

        // ===== gates layer 0 (own units, all 8 warps) + h0 exchange + LN partials =====
        {
            const float* zb = sm.z + gb * 128;
            float zi = zb[gj]      + zb[1024 + gj];
            float zf = zb[32 + gj] + zb[1024 + 32 + gj];
            float zg = zb[64 + gj] + zb[1024 + 64 + gj];
            float zo = zb[96 + gj] + zb[1024 + 96 + gj];
            int u = (int)rank * OWN + gj;
            float h = sm.hT0[par][gbp * RS + u * 2 + gdl];
            float c = sm.c0l[gb * OWN + gj];
            plstm_gate2(zi, zf, zg, zo, sm.tmb[par][gb],
                        sm.tau0s[gj], sm.itau0s[gj], sm.s0s[gj], h, c);
            sm.c0l[gb * OWN + gj] = c;
            bcast4_f32(&sm.hT0[parn][gbp * RS + u * 2 + gdl], h);
            float s = h, q = h * h;
            #pragma unroll
            for (int o = 16; o; o >>= 1) {
                s += __shfl_xor_sync(0xffffffffu, s, o);
                q += __shfl_xor_sync(0xffffffffu, q, o);
            }
            if (gj == 0) {
                bcast4_f32(&sm.red_s[rank * GC + gb], s);
                bcast4_f32(&sm.red_q[rank * GC + gb], q);
            }
        }
        CLUSTER_ARRIVE();                      // S1 arrive

        // ===== overlap S1: pre-fold z1 = Wh1 @ h1(t-1) + b1 + S2c (register acc) =====
        unsigned long long accW[2][2];
        {
            float4 s2v = *reinterpret_cast<const float4*>(&sm.S2cs[ks][lcq]);
            float c0 = s2v.x, c1 = s2v.y, c2 = s2v.z, c3 = s2v.w;
            if (ks == 0) {
                float4 b1v = *reinterpret_cast<const float4*>(&sm.b1s[lcq]);
                c0 += b1v.x; c1 += b1v.y; c2 += b1v.z; c3 += b1v.w;
            }
            accW[0][0] = pack2(c0, c1); accW[1][0] = pack2(c2, c3);
            accW[0][1] = accW[0][0];    accW[1][1] = accW[1][0];
            mv2(sm.Wh1s, &sm.hT1[par][bp * RS], kbase, quad, accW);
        }
        CLUSTER_WAIT();                        // S1 wait: hT0[parn] + LN partials visible

        // ===== z1 finish: A = Wx1g @ h0; z1 = accW + rs*A - rm*S1 =====
        {
            unsigned long long A[2][2];
            A[0][0] = 0ull; A[0][1] = 0ull; A[1][0] = 0ull; A[1][1] = 0ull;
            mv2(sm.Wx1g, &sm.hT0[parn][bp * RS], kbase, quad, A);
            float4 S1v = *reinterpret_cast<const float4*>(&sm.S1cs[ks][lcq]);
            unsigned long long S1a = pack2(S1v.x, S1v.y);
            unsigned long long S1b = pack2(S1v.z, S1v.w);
            float* zp = sm.z + ks * 1024 + (2 * bp) * 128 + lcq;
            #pragma unroll
            for (int d = 0; d < 2; ++d) {
                int b = 2 * bp + d;
                float s4 = sm.red_s[b] + sm.red_s[8 + b] + sm.red_s[16 + b] + sm.red_s[24 + b];
                float q4 = sm.red_q[b] + sm.red_q[8 + b] + sm.red_q[16 + b] + sm.red_q[24 + b];
                float mu  = s4 * (1.0f / 128.0f);
                float var = fmaxf(q4 * (1.0f / 128.0f) - mu * mu, 0.0f);
                float rs  = rsqrtf(var + LN_EPS_);
                float rm  = -rs * mu;
                unsigned long long rs2 = pack2(rs, rs);
                unsigned long long rm2 = pack2(rm, rm);
                fma2p(accW[0][d], rs2, A[0][d]);
                fma2p(accW[1][d], rs2, A[1][d]);
                fma2p(accW[0][d], rm2, S1a);
                fma2p(accW[1][d], rm2, S1b);
                *reinterpret_cast<unsigned long long*>(zp + d * 128)     = accW[0][d];
                *reinterpret_cast<unsigned long long*>(zp + d * 128 + 2) = accW[1][d];
            }
        }
        __syncthreads();                       // B3: z1 ready

        // ===== gates layer 1 (own units) + h1 exchange + in-warp FC partials =====
        {
            const float* zb = sm.z + gb * 128;
            float zi = zb[gj]      + zb[1024 + gj];
            float zf = zb[32 + gj] + zb[1024 + 32 + gj];
            float zg = zb[64 + gj] + zb[1024 + 64 + gj];
            float zo = zb[96 + gj] + zb[1024 + 96 + gj];
            int u = (int)rank * OWN + gj;
            float h = sm.hT1[par][gbp * RS + u * 2 + gdl];
            float c = sm.c1l[gb * OWN + gj];
            plstm_gate2(zi, zf, zg, zo, sm.tmb[par][gb],
                        sm.tau1s[gj], sm.itau1s[gj], sm.s1s[gj], h, c);
            sm.c1l[gb * OWN + gj] = c;
            bcast4_f32(&sm.hT1[parn][gbp * RS + u * 2 + gdl], h);
            // FC partial over this warp's 32 own units; lane = class (lanes 10-31 dummy)
            float a = 0.0f;
            #pragma unroll
            for (int j = 0; j < OWN; ++j)
                a += __shfl_sync(0xffffffffu, h, j) * sm.Wfcs[j * NC + gj];
            if (gj < NC) {
                int owner = gb >> 1, bL = gb & 1;
                uint32_t ad = (uint32_t)__cvta_generic_to_shared(
                    &sm.lrecv[((int)rank * 2 + bL) * 16 + gj]);
                st_cluster_f32(ad, (uint32_t)owner, a);
            }
        }
        __syncthreads();                       // B4: gates1 z-reads done
        CLUSTER_ARRIVE();                      // S2 arrive

        // ===== overlap S2: next step's layer-0 matvec + x/t prefetch =====
        if (t + 1 < TT) {
            unsigned long long acc[2][2];
            if (ks == 0) {
                float4 b0v = *reinterpret_cast<const float4*>(&sm.b0s[lcq]);
                float4 w0v = *reinterpret_cast<const float4*>(&sm.Wx0s[lcq]);
                float4 w1v = *reinterpret_cast<const float4*>(&sm.Wx0s[128 + lcq]);
                float4 w2v = *reinterpret_cast<const float4*>(&sm.Wx0s[256 + lcq]);
                #pragma unroll
                for (int d = 0; d < 2; ++d) {
                    const float* x = sm.xb[parn][2 * bp + d];
                    float xa = x[0], xb_ = x[1], xc = x[2];
                    float v0 = b0v.x + xa * w0v.x + xb_ * w1v.x + xc * w2v.x;
                    float v1 = b0v.y + xa * w0v.y + xb_ * w1v.y + xc * w2v.y;
                    float v2 = b0v.z + xa * w0v.z + xb_ * w1v.z + xc * w2v.z;
                    float v3 = b0v.w + xa * w0v.w + xb_ * w1v.w + xc * w2v.w;
                    acc[0][d] = pack2(v0, v1);
                    acc[1][d] = pack2(v2, v3);
                }
            } else {
                acc[0][0] = 0ull; acc[0][1] = 0ull; acc[1][0] = 0ull; acc[1][1] = 0ull;
            }
            mv2(sm.Wh0s, &sm.hT0[parn][bp * RS], kbase, quad, acc);   // h0(t), synced at S1
            float* zp = sm.z + ks * 1024 + (2 * bp) * 128 + lcq;
            *reinterpret_cast<unsigned long long*>(zp)           = acc[0][0];
            *reinterpret_cast<unsigned long long*>(zp + 2)       = acc[1][0];
            *reinterpret_cast<unsigned long long*>(zp + 128)     = acc[0][1];
            *reinterpret_cast<unsigned long long*>(zp + 130)     = acc[1][1];
            if (t + 2 < TT) {
                if (tid < GC)
                    sm.tmb[par][tid] = times[(size_t)(bstart + tid) * TT + t + 2];
                if (tid < GC * NF) {
                    int g = tid / NF, f = tid - g * NF;
                    sm.xb[par][g][f] = inputs[((size_t)(bstart + g) * TT + t + 2) * NF + f];
                }
            }
        }
        CLUSTER_WAIT();                        // S2 wait: hT1[parn] + logit partials visible

        // ===== warp-parallel softmax + output for this CTA's 2 batches =====
        if (tid < 32) {
            int bL = tid & 1, c2 = tid >> 1;       // lanes 0-19 valid (2 batches x 10 classes)
            bool valid = (c2 < NC);
            float lg = -1e30f;
            if (valid)
                lg = sm.bfcs[c2]
                   + sm.lrecv[(0 + bL) * 16 + c2] + sm.lrecv[(2 + bL) * 16 + c2]
                   + sm.lrecv[(4 + bL) * 16 + c2] + sm.lrecv[(6 + bL) * 16 + c2];
            float mx = lg;
            #pragma unroll
            for (int o = 2; o < 32; o <<= 1)
                mx = fmaxf(mx, __shfl_xor_sync(0xffffffffu, mx, o));
            float e = valid ? __expf(lg - mx) : 0.0f;
            float ssum = e;
            #pragma unroll
            for (int o = 2; o < 32; o <<= 1)
                ssum += __shfl_xor_sync(0xffffffffu, ssum, o);
            if (valid)
                out[((size_t)(bstart + (int)rank * 2 + bL) * TT + t) * NC + c2]
                    = e * __fdividef(1.0f, ssum);
        }
    }
}

extern "C" void kernel_launch(void* const* d_in, const int* in_sizes, int n_in,
                              void* d_out, int out_size) {
    const float* inputs = (const float*)d_in[0];
    const float* times  = (const float*)d_in[1];
    const float* Wx0    = (const float*)d_in[2];
    const float* Wh0    = (const float*)d_in[3];
    const float* b0     = (const float*)d_in[4];
    const float* tau0   = (const float*)d_in[5];
    const float* s0     = (const float*)d_in[6];
    const float* Wx1    = (const float*)d_in[7];
    const float* Wh1    = (const float*)d_in[8];
    const float* b1     = (const float*)d_in[9];
    const float* tau1   = (const float*)d_in[10];
    const float* s1     = (const float*)d_in[11];
    const float* gamma  = (const float*)d_in[12];
    const float* beta   = (const float*)d_in[13];
    const float* Wfc    = (const float*)d_in[14];
    const float* bfc    = (const float*)d_in[15];

    cudaFuncSetAttribute(plstm_cluster_kernel,
                         cudaFuncAttributeMaxDynamicSharedMemorySize,
                         (int)sizeof(SM));
    plstm_cluster_kernel<<<NCTA, NTHR, sizeof(SM)>>>(
        inputs, times, Wx0, Wh0, b0, tau0, s0,
        Wx1, Wh1, b1, tau1, s1, gamma, beta, Wfc, bfc, (float*)d_out);
}

// round 12
// speedup vs baseline: 1.4366x; 1.0512x over previous
#include <cuda_runtime.h>
#include <math.h>
#include <stdint.h>

// Problem constants
#define U      128
#define NC     10
#define NF     3
#define TT     1000
#define BB     256
#define CSZ    4              // CTAs per cluster
#define GC     8              // batch elements per cluster
#define OWN    32             // units owned per CTA
#define NTHR   256
#define NCTA   128            // (BB/GC)*CSZ
#define HR     132            // h row stride in floats ([b][u] layout, bank-skewed)

#define R_ON_   0.05f
#define ALPHA_  0.001f
#define LN_EPS_ 1e-3f

// ---- packed f32x2 helpers (FFMA2: 2x fp32 MAC throughput) ----
__device__ __forceinline__ unsigned long long pack2(float a, float b) {
    unsigned long long r;
    asm("mov.b64 %0, {%1, %2};" : "=l"(r) : "f"(a), "f"(b));
    return r;
}
__device__ __forceinline__ void fma2p(unsigned long long& acc,
                                      unsigned long long a,
                                      unsigned long long b) {
    asm("fma.rn.f32x2 %0, %1, %2, %0;" : "+l"(acc) : "l"(a), "l"(b));
}

// ---- fast transcendental helpers (rel err ~1e-6, budget is 1e-3) ----
__device__ __forceinline__ float fsig(float x) {
    return __fdividef(1.0f, 1.0f + __expf(-x));
}
__device__ __forceinline__ float ftanh(float x) {
    float ax = fabsf(x);
    float e  = __expf(-2.0f * ax);
    float t  = __fdividef(1.0f - e, 1.0f + e);
    return copysignf(t, x);
}

#define CLUSTER_ARRIVE() asm volatile("barrier.cluster.arrive.aligned;" ::: "memory")
#define CLUSTER_WAIT()   asm volatile("barrier.cluster.wait.aligned;"   ::: "memory")
#define CLUSTER_SYNC()   do { CLUSTER_ARRIVE(); CLUSTER_WAIT(); } while (0)

__device__ __forceinline__ void st_cluster_f32(uint32_t laddr, uint32_t r, float v) {
    uint32_t ra;
    asm volatile("mapa.shared::cluster.u32 %0, %1, %2;" : "=r"(ra) : "r"(laddr), "r"(r));
    asm volatile("st.shared::cluster.f32 [%0], %1;" :: "r"(ra), "f"(v) : "memory");
}
// store v to the same SMEM slot in all 4 cluster CTAs (incl. self)
__device__ __forceinline__ void bcast4_f32(void* p, float v) {
    uint32_t a = (uint32_t)__cvta_generic_to_shared(p);
    #pragma unroll
    for (uint32_t r = 0; r < CSZ; ++r) st_cluster_f32(a, r, v);
}

// Dynamic SMEM: ~231.7 KB (<= 232448 B limit, 1 CTA/SM)
struct __align__(16) SM {
    float Wh0s[128 * 128];      // own 128 cols (gate-interleaved) of Wh0, plain [k][lc]
    float Wx1g[128 * 128];      // own cols of Wx1 * gamma[k]
    float Wh1s[128 * 128];
    float z[2 * 8 * 128];       // [ks][b][lc] gate pre-activation partials
    float h0f[2][GC * HR];      // h0, [parity][b*HR + unit]  (lane-consecutive in u)
    float h1f[2][GC * HR];      // h1, same layout
    float c0l[GC * OWN], c1l[GC * OWN];  // own-unit cell state [b][j]
    float Wx0s[NF * 128];       // own cols of Wx0 [f][lc]
    float b0s[128], b1s[128];   // own cols of biases
    float S1cs[2][128];         // per-slab col sums of Wx1g
    float S2cs[2][128];         // per-slab col sums of Wx1*beta
    float tau0s[OWN], s0s[OWN], itau0s[OWN];
    float tau1s[OWN], s1s[OWN], itau1s[OWN];
    float Wfcs[OWN * NC + 32];  // own rows of Wfc (padded for OOB-safe reads)
    float bfcs[16];
    float red_s[CSZ * GC], red_q[CSZ * GC];   // LN partials [srcRank][b]
    float lrecv[CSZ * 2 * 16];  // logit partials [srcRank][localBatch][c pad16]
    float xb[2][GC][4];         // double-buffered inputs (f padded to 4)
    float tmb[2][GC];           // double-buffered times
};

// One 64-row K-slab: 4 cols (quad) x 2 batches (bpair) per thread.
// Ws plain [k][128]; hb0 = &h[b=2*bp][0] ([b][u] rows, stride HR).
// acc[p][d]: f32x2 over cols (quad*4+2p, +1) for batch 2*bp+d.
__device__ __forceinline__ void mv2(const float* __restrict__ Ws,
                                    const float* __restrict__ hb0,
                                    int kbase, int quad,
                                    unsigned long long acc[2][2]) {
    const ulonglong2* w2 = reinterpret_cast<const ulonglong2*>(Ws + kbase * 128) + quad;
    const float* h0p = hb0 + kbase;          // batch 2bp
    const float* h1p = hb0 + HR + kbase;     // batch 2bp+1
    #pragma unroll 8
    for (int k4 = 0; k4 < 16; ++k4) {
        float4 ha = *reinterpret_cast<const float4*>(h0p + 4 * k4);  // k..k+3, b even
        float4 hb = *reinterpret_cast<const float4*>(h1p + 4 * k4);  // k..k+3, b odd
        float hav[4] = {ha.x, ha.y, ha.z, ha.w};
        float hbv[4] = {hb.x, hb.y, hb.z, hb.w};
        #pragma unroll
        for (int j = 0; j < 4; ++j) {
            ulonglong2 w = w2[(4 * k4 + j) * 32];
            unsigned long long hd0 = pack2(hav[j], hav[j]);
            unsigned long long hd1 = pack2(hbv[j], hbv[j]);
            fma2p(acc[0][0], w.x, hd0); fma2p(acc[1][0], w.y, hd0);
            fma2p(acc[0][1], w.x, hd1); fma2p(acc[1][1], w.y, hd1);
        }
    }
}

// PhasedLSTM gate + time gate (fast mod via reciprocal + clamps; q < 1000 << 2^24)
__device__ __forceinline__ void plstm_gate2(float zi, float zf, float zg, float zo,
                                            float tcur, float tau, float itau, float s,
                                            float& h, float& c) {
    float ch = fsig(zf) * c + fsig(zi) * ftanh(zg);
    float hh = fsig(zo) * ftanh(ch);
    float d = tcur - s;
    float q = truncf(d * itau);
    float m = fmaf(-q, tau, d);
    m = (m < 0.0f)  ? m + tau : m;
    m = (m >= tau)  ? m - tau : m;
    m = (m < 0.0f)  ? m + tau : m;
    float phi = m * itau;
    float kg;
    if (phi < 0.5f * R_ON_)      kg = (2.0f * phi) / R_ON_;
    else if (phi < R_ON_)        kg = 2.0f - (2.0f * phi) / R_ON_;
    else                         kg = ALPHA_ * phi;
    h = kg * hh + (1.0f - kg) * h;
    c = kg * ch + (1.0f - kg) * c;
}

__global__ void __launch_bounds__(NTHR, 1) __cluster_dims__(CSZ, 1, 1)
plstm_cluster_kernel(const float* __restrict__ inputs, const float* __restrict__ times,
                     const float* __restrict__ gWx0, const float* __restrict__ gWh0,
                     const float* __restrict__ gb0,  const float* __restrict__ gtau0,
                     const float* __restrict__ gs0,  const float* __restrict__ gWx1,
                     const float* __restrict__ gWh1, const float* __restrict__ gb1,
                     const float* __restrict__ gtau1,const float* __restrict__ gs1,
                     const float* __restrict__ ggamma,const float* __restrict__ gbeta,
                     const float* __restrict__ gWfc, const float* __restrict__ gbfc,
                     float* __restrict__ out) {
    extern __shared__ float smraw[];
    SM& sm = *reinterpret_cast<SM*>(smraw);
    const int tid = threadIdx.x;
    uint32_t rank;
    asm("mov.u32 %0, %%cluster_ctarank;" : "=r"(rank));
    const int bstart = (blockIdx.x >> 2) * GC;

    // matvec mapping: 256 threads = 2 ks-slabs x (8 quads x 4 bpairs per warp-of-slab)
    const int ks    = tid >> 7;
    const int lane  = tid & 31;
    const int wq    = (tid >> 5) & 3;
    const int bp    = lane >> 3;            // batch pair (batches 2bp, 2bp+1)
    const int quad  = wq * 8 + (lane & 7);  // column quad (cols quad*4 .. +3)
    const int kbase = ks << 6;
    const int lcq   = quad * 4;
    // gate mapping: warp gb = batch, lane gj = own unit
    const int gb = tid >> 5, gj = lane;

    // ---- one-time SMEM setup: this CTA's column slabs (gate-interleaved cols) ----
    for (int i = tid; i < 128 * 128; i += NTHR) {
        int k = i >> 7, c = i & 127;
        int gcol = ((c >> 5) << 7) + ((int)rank << 5) + (c & 31);
        sm.Wh0s[i] = gWh0[k * 512 + gcol];
        sm.Wx1g[i] = gWx1[k * 512 + gcol];   // raw; scaled by gamma below
        sm.Wh1s[i] = gWh1[k * 512 + gcol];
    }
    for (int i = tid; i < NF * 128; i += NTHR) {
        int f = i >> 7, c = i & 127;
        int gcol = ((c >> 5) << 7) + ((int)rank << 5) + (c & 31);
        sm.Wx0s[i] = gWx0[f * 512 + gcol];
    }
    for (int c = tid; c < 128; c += NTHR) {
        int gcol = ((c >> 5) << 7) + ((int)rank << 5) + (c & 31);
        sm.b0s[c] = gb0[gcol];
        sm.b1s[c] = gb1[gcol];
    }
    if (tid < OWN) {
        int u = (int)rank * OWN + tid;
        float t0 = gtau0[u], t1 = gtau1[u];
        sm.tau0s[tid] = t0; sm.s0s[tid] = gs0[u]; sm.itau0s[tid] = 1.0f / t0;
        sm.tau1s[tid] = t1; sm.s1s[tid] = gs1[u]; sm.itau1s[tid] = 1.0f / t1;
    }
    for (int i = tid; i < OWN * NC + 32; i += NTHR)
        sm.Wfcs[i] = (i < OWN * NC) ? gWfc[((int)rank * OWN + i / NC) * NC + (i % NC)] : 0.0f;
    if (tid < NC) sm.bfcs[tid] = gbfc[tid];
    {
        float* p0 = &sm.h0f[0][0];
        float* p1 = &sm.h1f[0][0];
        for (int i = tid; i < 2 * GC * HR; i += NTHR) { p0[i] = 0.0f; p1[i] = 0.0f; }
    }
    sm.c0l[tid] = 0.0f; sm.c1l[tid] = 0.0f;
    if (tid < GC) {
        sm.tmb[0][tid] = times[(size_t)(bstart + tid) * TT];
        sm.tmb[1][tid] = times[(size_t)(bstart + tid) * TT + 1];
    }
    if (tid < GC * NF) {
        int g = tid / NF, f = tid - g * NF;
        sm.xb[0][g][f] = inputs[((size_t)(bstart + g) * TT) * NF + f];
        sm.xb[1][g][f] = inputs[((size_t)(bstart + g) * TT + 1) * NF + f];
    }
    __syncthreads();

    // ---- preload this thread's Wfc column into registers (FC uses shfl'd h) ----
    float wfcr[OWN];
    #pragma unroll
    for (int j = 0; j < OWN; ++j) wfcr[j] = sm.Wfcs[j * NC + gj];

    // ---- precompute: Wx1g *= gamma[k]; per-slab col sums S1 (Wx1*gm), S2 (Wx1*bt) ----
    {
        const int lc = tid & 127;
        float s1 = 0.0f, s2 = 0.0f;
        for (int k = 0; k < 64; ++k) {
            int kk = kbase + k;
            int ni = kk * 128 + lc;
            float w = sm.Wx1g[ni];
            float gm = ggamma[kk], bt = gbeta[kk];
            float wg = w * gm;
            sm.Wx1g[ni] = wg;
            s1 += wg;
            s2 += w * bt;
        }
        sm.S1cs[ks][lc] = s1;
        sm.S2cs[ks][lc] = s2;
    }
    __syncthreads();

    // ---- pre-loop: z0(0) = x(0)@Wx0 + b0 (h0 = 0, so no matvec needed) ----
    {
        float* zp = sm.z + ks * 1024 + (2 * bp) * 128 + lcq;
        if (ks == 0) {
            float4 b0v = *reinterpret_cast<const float4*>(&sm.b0s[lcq]);
            float4 w0v = *reinterpret_cast<const float4*>(&sm.Wx0s[lcq]);
            float4 w1v = *reinterpret_cast<const float4*>(&sm.Wx0s[128 + lcq]);
            float4 w2v = *reinterpret_cast<const float4*>(&sm.Wx0s[256 + lcq]);
            #pragma unroll
            for (int d = 0; d < 2; ++d) {
                const float* x = sm.xb[0][2 * bp + d];
                float xa = x[0], xb_ = x[1], xc = x[2];
                zp[d * 128 + 0] = b0v.x + xa * w0v.x + xb_ * w1v.x + xc * w2v.x;
                zp[d * 128 + 1] = b0v.y + xa * w0v.y + xb_ * w1v.y + xc * w2v.y;
                zp[d * 128 + 2] = b0v.z + xa * w0v.z + xb_ * w1v.z + xc * w2v.z;
                zp[d * 128 + 3] = b0v.w + xa * w0v.w + xb_ * w1v.w + xc * w2v.w;
            }
        } else {
            #pragma unroll
            for (int d = 0; d < 2; ++d) {
                zp[d * 128 + 0] = 0.0f; zp[d * 128 + 1] = 0.0f;
                zp[d * 128 + 2] = 0.0f; zp[d * 128 + 3] = 0.0f;
            }
        }
    }
    CLUSTER_SYNC();   // all CTAs initialized before any remote traffic

    for (int t = 0; t < TT; ++t) {
        const int par = t & 1, parn = par ^ 1;
        __syncthreads();                       // B1: z0 ready (pre-loop or tail of t-1)

        // ===== gates layer 0 (own units, all 8 warps) + h0 exchange + LN partials =====
        {
            const float* zb = sm.z + gb * 128;
            float zi = zb[gj]      + zb[1024 + gj];
            float zf = zb[32 + gj] + zb[1024 + 32 + gj];
            float zg = zb[64 + gj] + zb[1024 + 64 + gj];
            float zo = zb[96 + gj] + zb[1024 + 96 + gj];
            int u = (int)rank * OWN + gj;
            float h = sm.h0f[par][gb * HR + u];
            float c = sm.c0l[gb * OWN + gj];
            plstm_gate2(zi, zf, zg, zo, sm.tmb[par][gb],
                        sm.tau0s[gj], sm.itau0s[gj], sm.s0s[gj], h, c);
            sm.c0l[gb * OWN + gj] = c;
            bcast4_f32(&sm.h0f[parn][gb * HR + u], h);   // lane-consecutive remote store
            float s = h, q = h * h;
            #pragma unroll
            for (int o = 16; o; o >>= 1) {
                s += __shfl_xor_sync(0xffffffffu, s, o);
                q += __shfl_xor_sync(0xffffffffu, q, o);
            }
            if (gj == 0) {
                bcast4_f32(&sm.red_s[rank * GC + gb], s);
                bcast4_f32(&sm.red_q[rank * GC + gb], q);
            }
        }
        CLUSTER_ARRIVE();                      // S1 arrive

        // ===== overlap S1: pre-fold z1 = Wh1 @ h1(t-1) + b1 + S2c (register acc) =====
        unsigned long long accW[2][2];
        {
            float4 s2v = *reinterpret_cast<const float4*>(&sm.S2cs[ks][lcq]);
            float c0 = s2v.x, c1 = s2v.y, c2 = s2v.z, c3 = s2v.w;
            if (ks == 0) {
                float4 b1v = *reinterpret_cast<const float4*>(&sm.b1s[lcq]);
                c0 += b1v.x; c1 += b1v.y; c2 += b1v.z; c3 += b1v.w;
            }
            accW[0][0] = pack2(c0, c1); accW[1][0] = pack2(c2, c3);
            accW[0][1] = accW[0][0];    accW[1][1] = accW[1][0];
            mv2(sm.Wh1s, &sm.h1f[par][(2 * bp) * HR], kbase, quad, accW);
        }
        CLUSTER_WAIT();                        // S1 wait: h0f[parn] + LN partials visible

        // ===== z1 finish: A = Wx1g @ h0; z1 = accW + rs*A - rm*S1 =====
        {
            unsigned long long A[2][2];
            A[0][0] = 0ull; A[0][1] = 0ull; A[1][0] = 0ull; A[1][1] = 0ull;
            mv2(sm.Wx1g, &sm.h0f[parn][(2 * bp) * HR], kbase, quad, A);
            float4 S1v = *reinterpret_cast<const float4*>(&sm.S1cs[ks][lcq]);
            unsigned long long S1a = pack2(S1v.x, S1v.y);
            unsigned long long S1b = pack2(S1v.z, S1v.w);
            float* zp = sm.z + ks * 1024 + (2 * bp) * 128 + lcq;
            #pragma unroll
            for (int d = 0; d < 2; ++d) {
                int b = 2 * bp + d;
                float s4 = sm.red_s[b] + sm.red_s[8 + b] + sm.red_s[16 + b] + sm.red_s[24 + b];
                float q4 = sm.red_q[b] + sm.red_q[8 + b] + sm.red_q[16 + b] + sm.red_q[24 + b];
                float mu  = s4 * (1.0f / 128.0f);
                float var = fmaxf(q4 * (1.0f / 128.0f) - mu * mu, 0.0f);
                float rs  = rsqrtf(var + LN_EPS_);
                float rm  = -rs * mu;
                unsigned long long rs2 = pack2(rs, rs);
                unsigned long long rm2 = pack2(rm, rm);
                fma2p(accW[0][d], rs2, A[0][d]);
                fma2p(accW[1][d], rs2, A[1][d]);
                fma2p(accW[0][d], rm2, S1a);
                fma2p(accW[1][d], rm2, S1b);
                *reinterpret_cast<unsigned long long*>(zp + d * 128)     = accW[0][d];
                *reinterpret_cast<unsigned long long*>(zp + d * 128 + 2) = accW[1][d];
            }
        }
        __syncthreads();                       // B3: z1 ready

        // ===== gates layer 1 (own units) + h1 exchange + in-warp FC partials =====
        {
            const float* zb = sm.z + gb * 128;
            float zi = zb[gj]      + zb[1024 + gj];
            float zf = zb[32 + gj] + zb[1024 + 32 + gj];
            float zg = zb[64 + gj] + zb[1024 + 64 + gj];
            float zo = zb[96 + gj] + zb[1024 + 96 + gj];
            int u = (int)rank * OWN + gj;
            float h = sm.h1f[par][gb * HR + u];
            float c = sm.c1l[gb * OWN + gj];
            plstm_gate2(zi, zf, zg, zo, sm.tmb[par][gb],
                        sm.tau1s[gj], sm.itau1s[gj], sm.s1s[gj], h, c);
            sm.c1l[gb * OWN + gj] = c;
            bcast4_f32(&sm.h1f[parn][gb * HR + u], h);
            // FC partial over this warp's 32 own units; lane = class (lanes 10-31 dummy)
            float a = 0.0f;
            #pragma unroll
            for (int j = 0; j < OWN; ++j)
                a = fmaf(__shfl_sync(0xffffffffu, h, j), wfcr[j], a);
            if (gj < NC) {
                int owner = gb >> 1, bL = gb & 1;
                uint32_t ad = (uint32_t)__cvta_generic_to_shared(
                    &sm.lrecv[((int)rank * 2 + bL) * 16 + gj]);
                st_cluster_f32(ad, (uint32_t)owner, a);
            }
        }
        __syncthreads();                       // B4: gates1 z-reads done
        CLUSTER_ARRIVE();                      // S2 arrive

        // ===== overlap S2: next step's layer-0 matvec + x/t prefetch =====
        if (t + 1 < TT) {
            unsigned long long acc[2][2];
            if (ks == 0) {
                float4 b0v = *reinterpret_cast<const float4*>(&sm.b0s[lcq]);
                float4 w0v = *reinterpret_cast<const float4*>(&sm.Wx0s[lcq]);
                float4 w1v = *reinterpret_cast<const float4*>(&sm.Wx0s[128 + lcq]);
                float4 w2v = *reinterpret_cast<const float4*>(&sm.Wx0s[256 + lcq]);
                #pragma unroll
                for (int d = 0; d < 2; ++d) {
                    const float* x = sm.xb[parn][2 * bp + d];
                    float xa = x[0], xb_ = x[1], xc = x[2];
                    float v0 = b0v.x + xa * w0v.x + xb_ * w1v.x + xc * w2v.x;
                    float v1 = b0v.y + xa * w0v.y + xb_ * w1v.y + xc * w2v.y;
                    float v2 = b0v.z + xa * w0v.z + xb_ * w1v.z + xc * w2v.z;
                    float v3 = b0v.w + xa * w0v.w + xb_ * w1v.w + xc * w2v.w;
                    acc[0][d] = pack2(v0, v1);
                    acc[1][d] = pack2(v2, v3);
                }
            } else {
                acc[0][0] = 0ull; acc[0][1] = 0ull; acc[1][0] = 0ull; acc[1][1] = 0ull;
            }
            mv2(sm.Wh0s, &sm.h0f[parn][(2 * bp) * HR], kbase, quad, acc); // h0(t), synced at S1
            float* zp = sm.z + ks * 1024 + (2 * bp) * 128 + lcq;
            *reinterpret_cast<unsigned long long*>(zp)           = acc[0][0];
            *reinterpret_cast<unsigned long long*>(zp + 2)       = acc[1][0];
            *reinterpret_cast<unsigned long long*>(zp + 128)     = acc[0][1];
            *reinterpret_cast<unsigned long long*>(zp + 130)     = acc[1][1];
            if (t + 2 < TT) {
                if (tid < GC)
                    sm.tmb[par][tid] = times[(size_t)(bstart + tid) * TT + t + 2];
                if (tid < GC * NF) {
                    int g = tid / NF, f = tid - g * NF;
                    sm.xb[par][g][f] = inputs[((size_t)(bstart + g) * TT + t + 2) * NF + f];
                }
            }
        }
        CLUSTER_WAIT();                        // S2 wait: h1f[parn] + logit partials visible

        // ===== warp-parallel softmax + output for this CTA's 2 batches =====
        if (tid < 32) {
            int bL = tid & 1, c2 = tid >> 1;       // lanes 0-19 valid (2 batches x 10 classes)
            bool valid = (c2 < NC);
            float lg = -1e30f;
            if (valid)
                lg = sm.bfcs[c2]
                   + sm.lrecv[(0 + bL) * 16 + c2] + sm.lrecv[(2 + bL) * 16 + c2]
                   + sm.lrecv[(4 + bL) * 16 + c2] + sm.lrecv[(6 + bL) * 16 + c2];
            float mx = lg;
            #pragma unroll
            for (int o = 2; o < 32; o <<= 1)
                mx = fmaxf(mx, __shfl_xor_sync(0xffffffffu, mx, o));
            float e = valid ? __expf(lg - mx) : 0.0f;
            float ssum = e;
            #pragma unroll
            for (int o = 2; o < 32; o <<= 1)
                ssum += __shfl_xor_sync(0xffffffffu, ssum, o);
            if (valid)
                out[((size_t)(bstart + (int)rank * 2 + bL) * TT + t) * NC + c2]
                    = e * __fdividef(1.0f, ssum);
        }
    }
}

extern "C" void kernel_launch(void* const* d_in, const int* in_sizes, int n_in,
                              void* d_out, int out_size) {
    const float* inputs = (const float*)d_in[0];
    const float* times  = (const float*)d_in[1];
    const float* Wx0    = (const float*)d_in[2];
    const float* Wh0    = (const float*)d_in[3];
    const float* b0     = (const float*)d_in[4];
    const float* tau0   = (const float*)d_in[5];
    const float* s0     = (const float*)d_in[6];
    const float* Wx1    = (const float*)d_in[7];
    const float* Wh1    = (const float*)d_in[8];
    const float* b1     = (const float*)d_in[9];
    const float* tau1   = (const float*)d_in[10];
    const float* s1     = (const float*)d_in[11];
    const float* gamma  = (const float*)d_in[12];
    const float* beta   = (const float*)d_in[13];
    const float* Wfc    = (const float*)d_in[14];
    const float* bfc    = (const float*)d_in[15];

    cudaFuncSetAttribute(plstm_cluster_kernel,
                         cudaFuncAttributeMaxDynamicSharedMemorySize,
                         (int)sizeof(SM));
    plstm_cluster_kernel<<<NCTA, NTHR, sizeof(SM)>>>(
        inputs, times, Wx0, Wh0, b0, tau0, s0,
        Wx1, Wh1, b1, tau1, s1, gamma, beta, Wfc, bfc, (float*)d_out);
}

// round 13
// speedup vs baseline: 1.5673x; 1.0910x over previous
#include <cuda_runtime.h>
#include <math.h>
#include <stdint.h>

// Problem constants
#define U      128
#define NC     10
#define NF     3
#define TT     1000
#define BB     256
#define CSZ    4              // CTAs per cluster
#define GC     8              // batch elements per cluster
#define OWN    32             // units owned per CTA
#define NTHR   512            // 2 groups x 8 warps
#define NCTA   128            // (BB/GC)*CSZ
#define HR     132            // h row stride in floats ([b][u] layout, bank-skewed)

#define R_ON_   0.05f
#define ALPHA_  0.001f
#define LN_EPS_ 1e-3f

// ---- packed f32x2 helpers (FFMA2: 2x fp32 MAC throughput) ----
__device__ __forceinline__ unsigned long long pack2(float a, float b) {
    unsigned long long r;
    asm("mov.b64 %0, {%1, %2};" : "=l"(r) : "f"(a), "f"(b));
    return r;
}
__device__ __forceinline__ void fma2p(unsigned long long& acc,
                                      unsigned long long a,
                                      unsigned long long b) {
    asm("fma.rn.f32x2 %0, %1, %2, %0;" : "+l"(acc) : "l"(a), "l"(b));
}

// ---- fast transcendental helpers (rel err ~1e-6, budget is 1e-3) ----
__device__ __forceinline__ float fsig(float x) {
    return __fdividef(1.0f, 1.0f + __expf(-x));
}
__device__ __forceinline__ float ftanh(float x) {
    float ax = fabsf(x);
    float e  = __expf(-2.0f * ax);
    float t  = __fdividef(1.0f - e, 1.0f + e);
    return copysignf(t, x);
}

#define CLUSTER_ARRIVE() asm volatile("barrier.cluster.arrive.aligned;" ::: "memory")
#define CLUSTER_WAIT()   asm volatile("barrier.cluster.wait.aligned;"   ::: "memory")
#define CLUSTER_SYNC()   do { CLUSTER_ARRIVE(); CLUSTER_WAIT(); } while (0)

__device__ __forceinline__ void st_cluster_f32(uint32_t laddr, uint32_t r, float v) {
    uint32_t ra;
    asm volatile("mapa.shared::cluster.u32 %0, %1, %2;" : "=r"(ra) : "r"(laddr), "r"(r));
    asm volatile("st.shared::cluster.f32 [%0], %1;" :: "r"(ra), "f"(v) : "memory");
}
// store v to the same SMEM slot in all 4 cluster CTAs (incl. self)
__device__ __forceinline__ void bcast4_f32(void* p, float v) {
    uint32_t a = (uint32_t)__cvta_generic_to_shared(p);
    #pragma unroll
    for (uint32_t r = 0; r < CSZ; ++r) st_cluster_f32(a, r, v);
}

// Dynamic SMEM: ~232.2 KB worth? actual 232192 B <= 232448 limit (1 CTA/SM)
struct __align__(16) SM {
    float Wh0s[128 * 128];      // own 128 cols (gate-interleaved) of Wh0, plain [k][lc]
    float Wx1g[128 * 128];      // own cols of Wx1 * gamma[k]
    float Wh1s[128 * 128];
    float z[2 * 8 * 128];       // [ks][b][lc] gate pre-activations (also pre-fold buffer)
    float h0f[2][GC * HR];      // h0, [parity][b*HR + unit]
    float h1f[2][GC * HR];      // h1, same layout
    float c0l[GC * OWN], c1l[GC * OWN];  // own-unit cell state [b][j]
    float Wx0s[NF * 128];       // own cols of Wx0 [f][lc]
    float b0s[128], b1s[128];   // own cols of biases
    float S1cs[2][128];         // per-slab col sums of Wx1g
    float S2cs[2][128];         // per-slab col sums of Wx1*beta
    float tau0s[OWN], s0s[OWN], itau0s[OWN];
    float tau1s[OWN], s1s[OWN], itau1s[OWN];
    float Wfcs[OWN * NC + 32];  // own rows of Wfc (padded for OOB-safe reads)
    float bfcs[16];
    float red_s[CSZ * GC], red_q[CSZ * GC];   // LN partials [srcRank][b]
    float lrecv[2][CSZ * 2 * 16];  // logit partials, double-buffered by parity
    float xb[2][GC][4];         // double-buffered inputs (f padded to 4)
    float tmb[2][GC];           // double-buffered times
};

// One 64-row K-slab: 4 cols (quad) x 2 batches (bpair) per thread.
// Ws plain [k][128]; hb0 = &h[b=2*bp][0] ([b][u] rows, stride HR).
__device__ __forceinline__ void mv2(const float* __restrict__ Ws,
                                    const float* __restrict__ hb0,
                                    int kbase, int quad,
                                    unsigned long long acc[2][2]) {
    const ulonglong2* w2 = reinterpret_cast<const ulonglong2*>(Ws + kbase * 128) + quad;
    const float* h0p = hb0 + kbase;          // batch 2bp
    const float* h1p = hb0 + HR + kbase;     // batch 2bp+1
    #pragma unroll 8
    for (int k4 = 0; k4 < 16; ++k4) {
        float4 ha = *reinterpret_cast<const float4*>(h0p + 4 * k4);
        float4 hb = *reinterpret_cast<const float4*>(h1p + 4 * k4);
        float hav[4] = {ha.x, ha.y, ha.z, ha.w};
        float hbv[4] = {hb.x, hb.y, hb.z, hb.w};
        #pragma unroll
        for (int j = 0; j < 4; ++j) {
            ulonglong2 w = w2[(4 * k4 + j) * 32];
            unsigned long long hd0 = pack2(hav[j], hav[j]);
            unsigned long long hd1 = pack2(hbv[j], hbv[j]);
            fma2p(acc[0][0], w.x, hd0); fma2p(acc[1][0], w.y, hd0);
            fma2p(acc[0][1], w.x, hd1); fma2p(acc[1][1], w.y, hd1);
        }
    }
}

// PhasedLSTM gate + time gate (fast mod via reciprocal + clamps; q < 1000 << 2^24)
__device__ __forceinline__ void plstm_gate2(float zi, float zf, float zg, float zo,
                                            float tcur, float tau, float itau, float s,
                                            float& h, float& c) {
    float ch = fsig(zf) * c + fsig(zi) * ftanh(zg);
    float hh = fsig(zo) * ftanh(ch);
    float d = tcur - s;
    float q = truncf(d * itau);
    float m = fmaf(-q, tau, d);
    m = (m < 0.0f)  ? m + tau : m;
    m = (m >= tau)  ? m - tau : m;
    m = (m < 0.0f)  ? m + tau : m;
    float phi = m * itau;
    float kg;
    if (phi < 0.5f * R_ON_)      kg = (2.0f * phi) / R_ON_;
    else if (phi < R_ON_)        kg = 2.0f - (2.0f * phi) / R_ON_;
    else                         kg = ALPHA_ * phi;
    h = kg * hh + (1.0f - kg) * h;
    c = kg * ch + (1.0f - kg) * c;
}

__global__ void __launch_bounds__(NTHR, 1) __cluster_dims__(CSZ, 1, 1)
plstm_cluster_kernel(const float* __restrict__ inputs, const float* __restrict__ times,
                     const float* __restrict__ gWx0, const float* __restrict__ gWh0,
                     const float* __restrict__ gb0,  const float* __restrict__ gtau0,
                     const float* __restrict__ gs0,  const float* __restrict__ gWx1,
                     const float* __restrict__ gWh1, const float* __restrict__ gb1,
                     const float* __restrict__ gtau1,const float* __restrict__ gs1,
                     const float* __restrict__ ggamma,const float* __restrict__ gbeta,
                     const float* __restrict__ gWfc, const float* __restrict__ gbfc,
                     float* __restrict__ out) {
    extern __shared__ float smraw[];
    SM& sm = *reinterpret_cast<SM*>(smraw);
    const int tid = threadIdx.x;
    uint32_t rank;
    asm("mov.u32 %0, %%cluster_ctarank;" : "=r"(rank));
    const int bstart = (blockIdx.x >> 2) * GC;

    const bool isA = (tid < 256);
    // shared matvec mapping (both groups use their low-8 tid bits)
    const int mt    = tid & 255;
    const int ks    = mt >> 7;
    const int mlane = mt & 31;
    const int wq    = (mt >> 5) & 3;
    const int bp    = mlane >> 3;
    const int quad  = wq * 8 + (mlane & 7);
    const int kbase = ks << 6;
    const int lcq   = quad * 4;
    // gate mapping (A only): warp gb = batch, lane gj = own unit
    const int gb = tid >> 5, gj = tid & 31;

    // ---- one-time SMEM setup ----
    for (int i = tid; i < 128 * 128; i += NTHR) {
        int k = i >> 7, c = i & 127;
        int gcol = ((c >> 5) << 7) + ((int)rank << 5) + (c & 31);
        sm.Wh0s[i] = gWh0[k * 512 + gcol];
        sm.Wx1g[i] = gWx1[k * 512 + gcol];   // raw; scaled by gamma below
        sm.Wh1s[i] = gWh1[k * 512 + gcol];
    }
    for (int i = tid; i < NF * 128; i += NTHR) {
        int f = i >> 7, c = i & 127;
        int gcol = ((c >> 5) << 7) + ((int)rank << 5) + (c & 31);
        sm.Wx0s[i] = gWx0[f * 512 + gcol];
    }
    for (int c = tid; c < 128; c += NTHR) {
        int gcol = ((c >> 5) << 7) + ((int)rank << 5) + (c & 31);
        sm.b0s[c] = gb0[gcol];
        sm.b1s[c] = gb1[gcol];
    }
    if (tid < OWN) {
        int u = (int)rank * OWN + tid;
        float t0 = gtau0[u], t1 = gtau1[u];
        sm.tau0s[tid] = t0; sm.s0s[tid] = gs0[u]; sm.itau0s[tid] = 1.0f / t0;
        sm.tau1s[tid] = t1; sm.s1s[tid] = gs1[u]; sm.itau1s[tid] = 1.0f / t1;
    }
    for (int i = tid; i < OWN * NC + 32; i += NTHR)
        sm.Wfcs[i] = (i < OWN * NC) ? gWfc[((int)rank * OWN + i / NC) * NC + (i % NC)] : 0.0f;
    if (tid < NC) sm.bfcs[tid] = gbfc[tid];
    {
        float* p0 = &sm.h0f[0][0];
        float* p1 = &sm.h1f[0][0];
        for (int i = tid; i < 2 * GC * HR; i += NTHR) { p0[i] = 0.0f; p1[i] = 0.0f; }
    }
    if (tid < GC * OWN) { sm.c0l[tid] = 0.0f; sm.c1l[tid] = 0.0f; }
    if (tid < GC) {
        sm.tmb[0][tid] = times[(size_t)(bstart + tid) * TT];
        sm.tmb[1][tid] = times[(size_t)(bstart + tid) * TT + 1];
    }
    if (tid < GC * NF) {
        int g = tid / NF, f = tid - g * NF;
        sm.xb[0][g][f] = inputs[((size_t)(bstart + g) * TT) * NF + f];
        sm.xb[1][g][f] = inputs[((size_t)(bstart + g) * TT + 1) * NF + f];
    }
    __syncthreads();

    // ---- precompute (A threads): Wx1g *= gamma[k]; col sums S1, S2 ----
    if (isA) {
        const int lc = tid & 127;
        float s1 = 0.0f, s2 = 0.0f;
        for (int k = 0; k < 64; ++k) {
            int kk = kbase + k;
            int ni = kk * 128 + lc;
            float w = sm.Wx1g[ni];
            float wg = w * ggamma[kk];
            sm.Wx1g[ni] = wg;
            s1 += wg;
            s2 += w * gbeta[kk];
        }
        sm.S1cs[ks][lc] = s1;
        sm.S2cs[ks][lc] = s2;
    } else {
        // ---- pre-loop z0(0) = x(0)@Wx0 + b0 (h0 = 0) ----
        float* zp = sm.z + ks * 1024 + (2 * bp) * 128 + lcq;
        if (ks == 0) {
            float4 b0v = *reinterpret_cast<const float4*>(&sm.b0s[lcq]);
            float4 w0v = *reinterpret_cast<const float4*>(&sm.Wx0s[lcq]);
            float4 w1v = *reinterpret_cast<const float4*>(&sm.Wx0s[128 + lcq]);
            float4 w2v = *reinterpret_cast<const float4*>(&sm.Wx0s[256 + lcq]);
            #pragma unroll
            for (int d = 0; d < 2; ++d) {
                const float* x = sm.xb[0][2 * bp + d];
                float xa = x[0], xb_ = x[1], xc = x[2];
                zp[d * 128 + 0] = b0v.x + xa * w0v.x + xb_ * w1v.x + xc * w2v.x;
                zp[d * 128 + 1] = b0v.y + xa * w0v.y + xb_ * w1v.y + xc * w2v.y;
                zp[d * 128 + 2] = b0v.z + xa * w0v.z + xb_ * w1v.z + xc * w2v.z;
                zp[d * 128 + 3] = b0v.w + xa * w0v.w + xb_ * w1v.w + xc * w2v.w;
            }
        } else {
            #pragma unroll
            for (int d = 0; d < 2; ++d) {
                zp[d * 128 + 0] = 0.0f; zp[d * 128 + 1] = 0.0f;
                zp[d * 128 + 2] = 0.0f; zp[d * 128 + 3] = 0.0f;
            }
        }
    }
    CLUSTER_SYNC();   // all CTAs initialized before any remote traffic

    float* const zp = sm.z + ks * 1024 + (2 * bp) * 128 + lcq;

    for (int t = 0; t < TT; ++t) {
        const int par = t & 1, parn = par ^ 1;
        __syncthreads();                       // B1: z0(t) ready
        float tcur = 0.0f;                     // A caches its batch time (B clobbers tmb[par])
        unsigned long long acc0[2][2];         // B's next-z0 accumulator (lives across S2)

        // ===== P1: A: gates0 + h0 exchange + LN partials | B: Wh1@h1(t-1) pre-fold =====
        if (isA) {
            const float* zb = sm.z + gb * 128;
            float zi = zb[gj]      + zb[1024 + gj];
            float zf = zb[32 + gj] + zb[1024 + 32 + gj];
            float zg = zb[64 + gj] + zb[1024 + 64 + gj];
            float zo = zb[96 + gj] + zb[1024 + 96 + gj];
            int u = (int)rank * OWN + gj;
            tcur = sm.tmb[par][gb];
            float h = sm.h0f[par][gb * HR + u];
            float c = sm.c0l[gb * OWN + gj];
            plstm_gate2(zi, zf, zg, zo, tcur,
                        sm.tau0s[gj], sm.itau0s[gj], sm.s0s[gj], h, c);
            sm.c0l[gb * OWN + gj] = c;
            bcast4_f32(&sm.h0f[parn][gb * HR + u], h);
            float s = h, q = h * h;
            #pragma unroll
            for (int o = 16; o; o >>= 1) {
                s += __shfl_xor_sync(0xffffffffu, s, o);
                q += __shfl_xor_sync(0xffffffffu, q, o);
            }
            if (gj == 0) {
                bcast4_f32(&sm.red_s[rank * GC + gb], s);
                bcast4_f32(&sm.red_q[rank * GC + gb], q);
            }
        } else {
            unsigned long long accW[2][2];
            float4 s2v = *reinterpret_cast<const float4*>(&sm.S2cs[ks][lcq]);
            float c0 = s2v.x, c1 = s2v.y, c2 = s2v.z, c3 = s2v.w;
            if (ks == 0) {
                float4 b1v = *reinterpret_cast<const float4*>(&sm.b1s[lcq]);
                c0 += b1v.x; c1 += b1v.y; c2 += b1v.z; c3 += b1v.w;
            }
            accW[0][0] = pack2(c0, c1); accW[1][0] = pack2(c2, c3);
            accW[0][1] = accW[0][0];    accW[1][1] = accW[1][0];
            mv2(sm.Wh1s, &sm.h1f[par][(2 * bp) * HR], kbase, quad, accW);
            *reinterpret_cast<unsigned long long*>(zp)       = accW[0][0];
            *reinterpret_cast<unsigned long long*>(zp + 2)   = accW[1][0];
            *reinterpret_cast<unsigned long long*>(zp + 128) = accW[0][1];
            *reinterpret_cast<unsigned long long*>(zp + 130) = accW[1][1];
        }
        CLUSTER_SYNC();                        // S1: h0(t), LN partials, zW visible

        // ===== P2: A: Wx1g@h0 + LN fold -> z1 | B: softmax(t-1), prefetch, Wh0@h0 =====
        if (isA) {
            unsigned long long A[2][2];
            A[0][0] = 0ull; A[0][1] = 0ull; A[1][0] = 0ull; A[1][1] = 0ull;
            mv2(sm.Wx1g, &sm.h0f[parn][(2 * bp) * HR], kbase, quad, A);
            float4 S1v = *reinterpret_cast<const float4*>(&sm.S1cs[ks][lcq]);
            unsigned long long S1a = pack2(S1v.x, S1v.y);
            unsigned long long S1b = pack2(S1v.z, S1v.w);
            #pragma unroll
            for (int d = 0; d < 2; ++d) {
                int b = 2 * bp + d;
                float s4 = sm.red_s[b] + sm.red_s[8 + b] + sm.red_s[16 + b] + sm.red_s[24 + b];
                float q4 = sm.red_q[b] + sm.red_q[8 + b] + sm.red_q[16 + b] + sm.red_q[24 + b];
                float mu  = s4 * (1.0f / 128.0f);
                float var = fmaxf(q4 * (1.0f / 128.0f) - mu * mu, 0.0f);
                float rs  = rsqrtf(var + LN_EPS_);
                float rm  = -rs * mu;
                unsigned long long rs2 = pack2(rs, rs);
                unsigned long long rm2 = pack2(rm, rm);
                unsigned long long zw0 = *reinterpret_cast<unsigned long long*>(zp + d * 128);
                unsigned long long zw1 = *reinterpret_cast<unsigned long long*>(zp + d * 128 + 2);
                fma2p(zw0, rs2, A[0][d]); fma2p(zw0, rm2, S1a);
                fma2p(zw1, rs2, A[1][d]); fma2p(zw1, rm2, S1b);
                *reinterpret_cast<unsigned long long*>(zp + d * 128)     = zw0;
                *reinterpret_cast<unsigned long long*>(zp + d * 128 + 2) = zw1;
            }
        } else {
            // warp-parallel softmax for step t-1 (lrecv[parn], out row t-1)
            if (tid < 288 && t > 0) {
                int bL = tid & 1, c2 = (tid & 31) >> 1;
                bool valid = (c2 < NC);
                const float* lr = sm.lrecv[parn];
                float lg = -1e30f;
                if (valid)
                    lg = sm.bfcs[c2]
                       + lr[(0 + bL) * 16 + c2] + lr[(2 + bL) * 16 + c2]
                       + lr[(4 + bL) * 16 + c2] + lr[(6 + bL) * 16 + c2];
                float mx = lg;
                #pragma unroll
                for (int o = 2; o < 32; o <<= 1)
                    mx = fmaxf(mx, __shfl_xor_sync(0xffffffffu, mx, o));
                float e = valid ? __expf(lg - mx) : 0.0f;
                float ssum = e;
                #pragma unroll
                for (int o = 2; o < 32; o <<= 1)
                    ssum += __shfl_xor_sync(0xffffffffu, ssum, o);
                if (valid)
                    out[((size_t)(bstart + (int)rank * 2 + bL) * TT + (t - 1)) * NC + c2]
                        = e * __fdividef(1.0f, ssum);
            }
            // x/t prefetch for t+2 into slot par
            if (t + 2 < TT) {
                if (tid >= 288 && tid < 288 + GC)
                    sm.tmb[par][tid - 288] = times[(size_t)(bstart + (tid - 288)) * TT + t + 2];
                if (tid >= 296 && tid < 296 + GC * NF) {
                    int ii = tid - 296;
                    int g = ii / NF, f = ii - g * NF;
                    sm.xb[par][g][f] = inputs[((size_t)(bstart + g) * TT + t + 2) * NF + f];
                }
            }
            // next-z0 accumulate (registers; stored after S2)
            if (ks == 0) {
                float4 b0v = *reinterpret_cast<const float4*>(&sm.b0s[lcq]);
                float4 w0v = *reinterpret_cast<const float4*>(&sm.Wx0s[lcq]);
                float4 w1v = *reinterpret_cast<const float4*>(&sm.Wx0s[128 + lcq]);
                float4 w2v = *reinterpret_cast<const float4*>(&sm.Wx0s[256 + lcq]);
                #pragma unroll
                for (int d = 0; d < 2; ++d) {
                    const float* x = sm.xb[parn][2 * bp + d];
                    float xa = x[0], xb_ = x[1], xc = x[2];
                    float v0 = b0v.x + xa * w0v.x + xb_ * w1v.x + xc * w2v.x;
                    float v1 = b0v.y + xa * w0v.y + xb_ * w1v.y + xc * w2v.y;
                    float v2 = b0v.z + xa * w0v.z + xb_ * w1v.z + xc * w2v.z;
                    float v3 = b0v.w + xa * w0v.w + xb_ * w1v.w + xc * w2v.w;
                    acc0[0][d] = pack2(v0, v1);
                    acc0[1][d] = pack2(v2, v3);
                }
            } else {
                acc0[0][0] = 0ull; acc0[0][1] = 0ull; acc0[1][0] = 0ull; acc0[1][1] = 0ull;
            }
            mv2(sm.Wh0s, &sm.h0f[parn][(2 * bp) * HR], kbase, quad, acc0);
        }
        __syncthreads();                       // B3: z1 ready

        // ===== P3: A: gates1 + h1 exchange + FC partials | B: idle (arrives S2) =====
        if (isA) {
            const float* zb = sm.z + gb * 128;
            float zi = zb[gj]      + zb[1024 + gj];
            float zf = zb[32 + gj] + zb[1024 + 32 + gj];
            float zg = zb[64 + gj] + zb[1024 + 64 + gj];
            float zo = zb[96 + gj] + zb[1024 + 96 + gj];
            int u = (int)rank * OWN + gj;
            float h = sm.h1f[par][gb * HR + u];
            float c = sm.c1l[gb * OWN + gj];
            plstm_gate2(zi, zf, zg, zo, tcur,
                        sm.tau1s[gj], sm.itau1s[gj], sm.s1s[gj], h, c);
            sm.c1l[gb * OWN + gj] = c;
            bcast4_f32(&sm.h1f[parn][gb * HR + u], h);
            float a = 0.0f;
            #pragma unroll
            for (int j = 0; j < OWN; ++j)
                a = fmaf(__shfl_sync(0xffffffffu, h, j), sm.Wfcs[j * NC + gj], a);
            if (gj < NC) {
                int owner = gb >> 1, bL = gb & 1;
                uint32_t ad = (uint32_t)__cvta_generic_to_shared(
                    &sm.lrecv[par][((int)rank * 2 + bL) * 16 + gj]);
                st_cluster_f32(ad, (uint32_t)owner, a);
            }
        }
        CLUSTER_SYNC();                        // S2: h1(t), lrecv(t) visible; z free

        // ===== P4: B stores next-z0 =====
        if (!isA && t + 1 < TT) {
            *reinterpret_cast<unsigned long long*>(zp)       = acc0[0][0];
            *reinterpret_cast<unsigned long long*>(zp + 2)   = acc0[1][0];
            *reinterpret_cast<unsigned long long*>(zp + 128) = acc0[0][1];
            *reinterpret_cast<unsigned long long*>(zp + 130) = acc0[1][1];
        }
    }

    // ===== epilogue: softmax for the final step (TT-1) =====
    if (tid >= 256 && tid < 288) {
        const int pe = (TT - 1) & 1;
        int bL = tid & 1, c2 = (tid & 31) >> 1;
        bool valid = (c2 < NC);
        const float* lr = sm.lrecv[pe];
        float lg = -1e30f;
        if (valid)
            lg = sm.bfcs[c2]
               + lr[(0 + bL) * 16 + c2] + lr[(2 + bL) * 16 + c2]
               + lr[(4 + bL) * 16 + c2] + lr[(6 + bL) * 16 + c2];
        float mx = lg;
        #pragma unroll
        for (int o = 2; o < 32; o <<= 1)
            mx = fmaxf(mx, __shfl_xor_sync(0xffffffffu, mx, o));
        float e = valid ? __expf(lg - mx) : 0.0f;
        float ssum = e;
        #pragma unroll
        for (int o = 2; o < 32; o <<= 1)
            ssum += __shfl_xor_sync(0xffffffffu, ssum, o);
        if (valid)
            out[((size_t)(bstart + (int)rank * 2 + bL) * TT + (TT - 1)) * NC + c2]
                = e * __fdividef(1.0f, ssum);
    }
}

extern "C" void kernel_launch(void* const* d_in, const int* in_sizes, int n_in,
                              void* d_out, int out_size) {
    const float* inputs = (const float*)d_in[0];
    const float* times  = (const float*)d_in[1];
    const float* Wx0    = (const float*)d_in[2];
    const float* Wh0    = (const float*)d_in[3];
    const float* b0     = (const float*)d_in[4];
    const float* tau0   = (const float*)d_in[5];
    const float* s0     = (const float*)d_in[6];
    const float* Wx1    = (const float*)d_in[7];
    const float* Wh1    = (const float*)d_in[8];
    const float* b1     = (const float*)d_in[9];
    const float* tau1   = (const float*)d_in[10];
    const float* s1     = (const float*)d_in[11];
    const float* gamma  = (const float*)d_in[12];
    const float* beta   = (const float*)d_in[13];
    const float* Wfc    = (const float*)d_in[14];
    const float* bfc    = (const float*)d_in[15];

    cudaFuncSetAttribute(plstm_cluster_kernel,
                         cudaFuncAttributeMaxDynamicSharedMemorySize,
                         (int)sizeof(SM));
    plstm_cluster_kernel<<<NCTA, NTHR, sizeof(SM)>>>(
        inputs, times, Wx0, Wh0, b0, tau0, s0,
        Wx1, Wh1, b1, tau1, s1, gamma, beta, Wfc, bfc, (float*)d_out);
}